// round 3
// baseline (speedup 1.0000x reference)
#include <cuda_runtime.h>
#include <cuda_bf16.h>
#include <math.h>

// Problem constants (fixed by the dataset)
#define NN 100000
#define EE 3200000
#define FD 128    // in/hidden feature dim
#define CD 32     // classes

// ---------------------------------------------------------------------------
// Scratch (static device globals: no allocation allowed in kernel_launch)
// ---------------------------------------------------------------------------
__device__ float g_H[NN * FD];     // GEMM output  (51.2 MB)
__device__ float g_G[NN * FD];     // aggregation accumulator (51.2 MB)
__device__ float g_dinv[NN];       // degree, then deg^-0.5
__device__ float g_norm[EE];       // per-edge symmetric norm
__device__ int   g_src[EE];
__device__ int   g_dst[EE];
__device__ int   g_is64;           // edge_index dtype flag

// ---------------------------------------------------------------------------
// Preprocessing kernels
// ---------------------------------------------------------------------------
__global__ void k_detect_dtype(const long long* __restrict__ ei) {
    if (blockIdx.x == 0 && threadIdx.x == 0) {
        int ok = 1;
        for (int i = 0; i < 128; i++) {
            long long v = ei[i];
            if (v < 0 || v >= (long long)NN) { ok = 0; break; }
        }
        g_is64 = ok;
    }
}

__global__ void k_init_deg(float* __restrict__ dinv) {
    int i = blockIdx.x * blockDim.x + threadIdx.x;
    if (i < NN) dinv[i] = 1.0f;   // self-loop contributes 1 to degree
}

// Convert edge list to int32 and accumulate degrees over dst.
__global__ void k_edges(const long long* __restrict__ ei,
                        int* __restrict__ src, int* __restrict__ dst,
                        float* __restrict__ deg) {
    int e = blockIdx.x * blockDim.x + threadIdx.x;
    if (e >= EE) return;
    int s, d;
    if (g_is64) {
        s = (int)ei[e];
        d = (int)ei[EE + e];
    } else {
        const int* ei32 = (const int*)ei;
        s = ei32[e];
        d = ei32[EE + e];
    }
    src[e] = s;
    dst[e] = d;
    atomicAdd(&deg[d], 1.0f);
}

__global__ void k_dinv(float* __restrict__ dinv) {
    int i = blockIdx.x * blockDim.x + threadIdx.x;
    if (i < NN) dinv[i] = rsqrtf(dinv[i]);   // deg >= 1 always (self-loop)
}

__global__ void k_norm(const int* __restrict__ src, const int* __restrict__ dst,
                       const float* __restrict__ dinv, float* __restrict__ norm) {
    int e = blockIdx.x * blockDim.x + threadIdx.x;
    if (e >= EE) return;
    norm[e] = dinv[src[e]] * dinv[dst[e]];
}

// ---------------------------------------------------------------------------
// SGEMM: Hout[M, Ncols] = act(A[M, K]) @ W[K, Ncols]
// act = ReLU on load when RELU (bias was already folded into A by k_initG).
// ---------------------------------------------------------------------------
template <int BM, int BN, int BK, int TM, int TN, bool RELU>
__global__ void __launch_bounds__((BM / TM) * (BN / TN))
k_gemm(const float* __restrict__ A, const float* __restrict__ W,
       float* __restrict__ Hout, int M, int K, int Ncols) {
    constexpr int NT = (BM / TM) * (BN / TN);
    __shared__ float As[BK][BM];
    __shared__ float Bs[BK][BN];

    const int tid  = threadIdx.x;
    const int tx   = tid % (BN / TN);
    const int ty   = tid / (BN / TN);
    const int row0 = blockIdx.y * BM;
    const int col0 = blockIdx.x * BN;

    float acc[TM][TN];
#pragma unroll
    for (int i = 0; i < TM; i++)
#pragma unroll
        for (int j = 0; j < TN; j++) acc[i][j] = 0.0f;

    for (int k0 = 0; k0 < K; k0 += BK) {
        // Load A tile (transposed into As[k][m]), zero-pad past M, fused ReLU.
        for (int i = tid; i < BM * BK / 4; i += NT) {
            int m  = i / (BK / 4);
            int kq = i % (BK / 4);
            int r  = row0 + m;
            float4 v = make_float4(0.f, 0.f, 0.f, 0.f);
            if (r < M) v = *(const float4*)&A[(size_t)r * K + k0 + kq * 4];
            if (RELU) {
                v.x = fmaxf(v.x, 0.f); v.y = fmaxf(v.y, 0.f);
                v.z = fmaxf(v.z, 0.f); v.w = fmaxf(v.w, 0.f);
            }
            As[kq * 4 + 0][m] = v.x;
            As[kq * 4 + 1][m] = v.y;
            As[kq * 4 + 2][m] = v.z;
            As[kq * 4 + 3][m] = v.w;
        }
        // Load B tile.
        for (int i = tid; i < BK * BN / 4; i += NT) {
            int kr = i / (BN / 4);
            int cq = i % (BN / 4);
            *(float4*)&Bs[kr][cq * 4] =
                *(const float4*)&W[(size_t)(k0 + kr) * Ncols + col0 + cq * 4];
        }
        __syncthreads();

#pragma unroll
        for (int k = 0; k < BK; k++) {
            float a[TM], b[TN];
#pragma unroll
            for (int j = 0; j < TM; j += 4) {
                float4 t = *(const float4*)&As[k][ty * TM + j];
                a[j] = t.x; a[j + 1] = t.y; a[j + 2] = t.z; a[j + 3] = t.w;
            }
#pragma unroll
            for (int j = 0; j < TN; j += 4) {
                float4 t = *(const float4*)&Bs[k][tx * TN + j];
                b[j] = t.x; b[j + 1] = t.y; b[j + 2] = t.z; b[j + 3] = t.w;
            }
#pragma unroll
            for (int i = 0; i < TM; i++)
#pragma unroll
                for (int j = 0; j < TN; j++)
                    acc[i][j] = fmaf(a[i], b[j], acc[i][j]);
        }
        __syncthreads();
    }

    // Store
#pragma unroll
    for (int i = 0; i < TM; i++) {
        int r = row0 + ty * TM + i;
        if (r < M) {
#pragma unroll
            for (int j = 0; j < TN; j += 4) {
                float4 v = make_float4(acc[i][j], acc[i][j + 1],
                                       acc[i][j + 2], acc[i][j + 3]);
                *(float4*)&Hout[(size_t)r * Ncols + col0 + tx * TN + j] = v;
            }
        }
    }
}

// ---------------------------------------------------------------------------
// G init: bias + self-loop contribution. G[i,:] = b + H[i,:] * dinv[i]^2
// ---------------------------------------------------------------------------
template <int C>
__global__ void k_initG(const float* __restrict__ H, const float* __restrict__ bias,
                        const float* __restrict__ dinv, float* __restrict__ G) {
    int idx = blockIdx.x * blockDim.x + threadIdx.x;   // over NN * C / 4
    if (idx >= NN * (C / 4)) return;
    int i  = idx / (C / 4);
    int c4 = idx % (C / 4);
    float dv = dinv[i];
    float w  = dv * dv;
    float4 h = *(const float4*)&H[idx * 4];
    float4 b = *(const float4*)&bias[c4 * 4];
    float4 g;
    g.x = fmaf(h.x, w, b.x);
    g.y = fmaf(h.y, w, b.y);
    g.z = fmaf(h.z, w, b.z);
    g.w = fmaf(h.w, w, b.w);
    *(float4*)&G[idx * 4] = g;
}

// ---------------------------------------------------------------------------
// Scatter-aggregate: G[dst,:] += H[src,:] * norm  (vector RED, no return)
// ---------------------------------------------------------------------------
__device__ __forceinline__ void red_add_v4(float* p, float4 v) {
    asm volatile("red.global.add.v4.f32 [%0], {%1, %2, %3, %4};"
                 :: "l"(p), "f"(v.x), "f"(v.y), "f"(v.z), "f"(v.w)
                 : "memory");
}

__global__ void k_scatter128(const float* __restrict__ H, float* __restrict__ G,
                             const int* __restrict__ src, const int* __restrict__ dst,
                             const float* __restrict__ norm) {
    int t = blockIdx.x * blockDim.x + threadIdx.x;
    int e = t >> 5;
    if (e >= EE) return;
    int lane = t & 31;
    int s = src[e], d = dst[e];
    float w = norm[e];
    float4 v = *(const float4*)&H[(size_t)s * 128 + lane * 4];
    v.x *= w; v.y *= w; v.z *= w; v.w *= w;
    red_add_v4(&G[(size_t)d * 128 + lane * 4], v);
}

__global__ void k_scatter32(const float* __restrict__ H, float* __restrict__ G,
                            const int* __restrict__ src, const int* __restrict__ dst,
                            const float* __restrict__ norm) {
    int t = blockIdx.x * blockDim.x + threadIdx.x;
    int e = t >> 3;
    if (e >= EE) return;
    int sub = t & 7;
    int s = src[e], d = dst[e];
    float w = norm[e];
    float4 v = *(const float4*)&H[(size_t)s * 32 + sub * 4];
    v.x *= w; v.y *= w; v.z *= w; v.w *= w;
    red_add_v4(&G[(size_t)d * 32 + sub * 4], v);
}

// ---------------------------------------------------------------------------
// Final log-softmax over 32 classes: one warp per row.
// ---------------------------------------------------------------------------
__global__ void k_log_softmax(const float* __restrict__ G, float* __restrict__ out) {
    int t = blockIdx.x * blockDim.x + threadIdx.x;
    int i = t >> 5;
    if (i >= NN) return;
    int lane = t & 31;
    float v = G[i * 32 + lane];
    float mx = v;
#pragma unroll
    for (int o = 16; o > 0; o >>= 1)
        mx = fmaxf(mx, __shfl_xor_sync(0xFFFFFFFFu, mx, o));
    float ex = expf(v - mx);
#pragma unroll
    for (int o = 16; o > 0; o >>= 1)
        ex += __shfl_xor_sync(0xFFFFFFFFu, ex, o);
    out[i * 32 + lane] = v - mx - logf(ex);
}

// ---------------------------------------------------------------------------
// Launch
// ---------------------------------------------------------------------------
extern "C" void kernel_launch(void* const* d_in, const int* in_sizes, int n_in,
                              void* d_out, int out_size) {
    const float*     x  = (const float*)d_in[0];
    const long long* ei = (const long long*)d_in[1];
    const float* W1 = (const float*)d_in[2];
    const float* b1 = (const float*)d_in[3];
    const float* W2 = (const float*)d_in[4];
    const float* b2 = (const float*)d_in[5];
    const float* W3 = (const float*)d_in[6];
    const float* b3 = (const float*)d_in[7];
    const float* W4 = (const float*)d_in[8];
    const float* b4 = (const float*)d_in[9];
    float* out = (float*)d_out;

    float *H, *G, *dinv, *norm;
    int *src, *dst;
    cudaGetSymbolAddress((void**)&H,    g_H);
    cudaGetSymbolAddress((void**)&G,    g_G);
    cudaGetSymbolAddress((void**)&dinv, g_dinv);
    cudaGetSymbolAddress((void**)&norm, g_norm);
    cudaGetSymbolAddress((void**)&src,  g_src);
    cudaGetSymbolAddress((void**)&dst,  g_dst);

    const int TB = 256;

    // --- graph preprocessing ---
    k_detect_dtype<<<1, 32>>>(ei);
    k_init_deg<<<(NN + TB - 1) / TB, TB>>>(dinv);
    k_edges<<<(EE + TB - 1) / TB, TB>>>(ei, src, dst, dinv);
    k_dinv<<<(NN + TB - 1) / TB, TB>>>(dinv);
    k_norm<<<(EE + TB - 1) / TB, TB>>>(src, dst, dinv, norm);

    const dim3 gemm_grid(1, (NN + 127) / 128);
    const int  sc128_blocks = (EE * 32 + TB - 1) / TB;
    const int  sc32_blocks  = (EE * 8 + TB - 1) / TB;
    const int  init128_blocks = (NN * 32 + TB - 1) / TB;
    const int  init32_blocks  = (NN * 8 + TB - 1) / TB;

    // --- layer 1 (input x, no ReLU on load) ---
    k_gemm<128, 128, 8, 8, 8, false><<<gemm_grid, 256>>>(x, W1, H, NN, FD, FD);
    k_initG<128><<<init128_blocks, TB>>>(H, b1, dinv, G);
    k_scatter128<<<sc128_blocks, TB>>>(H, G, src, dst, norm);

    // --- layer 2 ---
    k_gemm<128, 128, 8, 8, 8, true><<<gemm_grid, 256>>>(G, W2, H, NN, FD, FD);
    k_initG<128><<<init128_blocks, TB>>>(H, b2, dinv, G);
    k_scatter128<<<sc128_blocks, TB>>>(H, G, src, dst, norm);

    // --- layer 3 ---
    k_gemm<128, 128, 8, 8, 8, true><<<gemm_grid, 256>>>(G, W3, H, NN, FD, FD);
    k_initG<128><<<init128_blocks, TB>>>(H, b3, dinv, G);
    k_scatter128<<<sc128_blocks, TB>>>(H, G, src, dst, norm);

    // --- layer 4 (32 classes) ---
    k_gemm<128, 32, 8, 8, 4, true><<<gemm_grid, 128>>>(G, W4, H, NN, FD, CD);
    k_initG<32><<<init32_blocks, TB>>>(H, b4, dinv, G);
    k_scatter32<<<sc32_blocks, TB>>>(H, G, src, dst, norm);

    // --- log-softmax ---
    k_log_softmax<<<(NN * 32 + TB - 1) / TB, TB>>>(G, out);
}

// round 4
// speedup vs baseline: 2.4591x; 2.4591x over previous
#include <cuda_runtime.h>
#include <cuda_bf16.h>
#include <math.h>

// Problem constants (fixed by the dataset)
#define NN 100000
#define EE 3200000
#define FD 128    // in/hidden feature dim
#define CD 32     // classes
#define NTILES ((NN + 255) / 256)   // 391

// ---------------------------------------------------------------------------
// Scratch (static device globals: no allocation allowed in kernel_launch)
// ---------------------------------------------------------------------------
__device__ float g_H[NN * FD];        // GEMM output        (51.2 MB)
__device__ float g_G[NN * FD];        // aggregated output  (51.2 MB)
__device__ float g_dinv[NN];          // deg^-0.5
__device__ int   g_cnt[NN];           // degree histogram (no self-loop)
__device__ int   g_off[NN + 1];       // CSR row offsets (by dst)
__device__ int   g_cursor[NN];        // fill cursors
__device__ int   g_tileSum[NTILES];
__device__ int   g_tileBase[NTILES];
__device__ int   g_csr_src[EE];       // 12.8 MB
__device__ float g_csr_w[EE];         // 12.8 MB
__device__ int   g_is64;              // edge_index dtype flag

// ---------------------------------------------------------------------------
// Preprocessing
// ---------------------------------------------------------------------------
__global__ void k_detect_dtype(const long long* __restrict__ ei) {
    if (blockIdx.x == 0 && threadIdx.x == 0) {
        int ok = 1;
        for (int i = 0; i < 128; i++) {
            long long v = ei[i];
            if (v < 0 || v >= (long long)NN) { ok = 0; break; }
        }
        g_is64 = ok;
    }
}

__global__ void k_zero_cnt(int* __restrict__ cnt) {
    int i = blockIdx.x * blockDim.x + threadIdx.x;
    if (i < NN) cnt[i] = 0;
}

__global__ void k_hist(const long long* __restrict__ ei, int* __restrict__ cnt) {
    int e = blockIdx.x * blockDim.x + threadIdx.x;
    if (e >= EE) return;
    int d = g_is64 ? (int)ei[EE + e] : ((const int*)ei)[EE + e];
    atomicAdd(&cnt[d], 1);
}

__global__ void k_dinv(const int* __restrict__ cnt, float* __restrict__ dinv) {
    int i = blockIdx.x * blockDim.x + threadIdx.x;
    if (i < NN) dinv[i] = rsqrtf((float)(cnt[i] + 1));  // +1 self-loop
}

__global__ void k_tile_sums(const int* __restrict__ cnt, int* __restrict__ tileSum) {
    __shared__ int sh[256];
    int t = threadIdx.x;
    int i = blockIdx.x * 256 + t;
    sh[t] = (i < NN) ? cnt[i] : 0;
    __syncthreads();
#pragma unroll
    for (int s = 128; s > 0; s >>= 1) {
        if (t < s) sh[t] += sh[t + s];
        __syncthreads();
    }
    if (t == 0) tileSum[blockIdx.x] = sh[0];
}

__global__ void k_scan_tilesums(const int* __restrict__ tileSum,
                                int* __restrict__ tileBase) {
    __shared__ int sh[512];
    int t = threadIdx.x;
    int v = (t < NTILES) ? tileSum[t] : 0;
    sh[t] = v;
    __syncthreads();
#pragma unroll
    for (int o = 1; o < 512; o <<= 1) {
        int a = (t >= o) ? sh[t - o] : 0;
        __syncthreads();
        sh[t] += a;
        __syncthreads();
    }
    if (t < NTILES) tileBase[t] = sh[t] - v;   // exclusive
}

__global__ void k_scan_within(const int* __restrict__ cnt,
                              const int* __restrict__ tileBase,
                              int* __restrict__ off, int* __restrict__ cursor) {
    __shared__ int sh[256];
    int t = threadIdx.x;
    int i = blockIdx.x * 256 + t;
    int v = (i < NN) ? cnt[i] : 0;
    sh[t] = v;
    __syncthreads();
#pragma unroll
    for (int o = 1; o < 256; o <<= 1) {
        int a = (t >= o) ? sh[t - o] : 0;
        __syncthreads();
        sh[t] += a;
        __syncthreads();
    }
    int incl = sh[t];
    if (i < NN) {
        int ex = tileBase[blockIdx.x] + incl - v;
        off[i] = ex;
        cursor[i] = ex;
        if (i == NN - 1) off[NN] = tileBase[blockIdx.x] + incl;
    }
}

__global__ void k_fill(const long long* __restrict__ ei,
                       const float* __restrict__ dinv,
                       int* __restrict__ cursor,
                       int* __restrict__ csr_src, float* __restrict__ csr_w) {
    int e = blockIdx.x * blockDim.x + threadIdx.x;
    if (e >= EE) return;
    int s, d;
    if (g_is64) {
        s = (int)ei[e];
        d = (int)ei[EE + e];
    } else {
        const int* ei32 = (const int*)ei;
        s = ei32[e];
        d = ei32[EE + e];
    }
    int pos = atomicAdd(&cursor[d], 1);
    csr_src[pos] = s;
    csr_w[pos]   = dinv[s] * dinv[d];
}

// ---------------------------------------------------------------------------
// SGEMM: Hout[M, Ncols] = act(A[M, K]) @ W[K, Ncols]; ReLU fused on load.
// ---------------------------------------------------------------------------
template <int BM, int BN, int BK, int TM, int TN, bool RELU>
__global__ void __launch_bounds__((BM / TM) * (BN / TN))
k_gemm(const float* __restrict__ A, const float* __restrict__ W,
       float* __restrict__ Hout, int M, int K, int Ncols) {
    constexpr int NT = (BM / TM) * (BN / TN);
    __shared__ float As[BK][BM];
    __shared__ float Bs[BK][BN];

    const int tid  = threadIdx.x;
    const int tx   = tid % (BN / TN);
    const int ty   = tid / (BN / TN);
    const int row0 = blockIdx.y * BM;
    const int col0 = blockIdx.x * BN;

    float acc[TM][TN];
#pragma unroll
    for (int i = 0; i < TM; i++)
#pragma unroll
        for (int j = 0; j < TN; j++) acc[i][j] = 0.0f;

    for (int k0 = 0; k0 < K; k0 += BK) {
        for (int i = tid; i < BM * BK / 4; i += NT) {
            int m  = i / (BK / 4);
            int kq = i % (BK / 4);
            int r  = row0 + m;
            float4 v = make_float4(0.f, 0.f, 0.f, 0.f);
            if (r < M) v = *(const float4*)&A[(size_t)r * K + k0 + kq * 4];
            if (RELU) {
                v.x = fmaxf(v.x, 0.f); v.y = fmaxf(v.y, 0.f);
                v.z = fmaxf(v.z, 0.f); v.w = fmaxf(v.w, 0.f);
            }
            As[kq * 4 + 0][m] = v.x;
            As[kq * 4 + 1][m] = v.y;
            As[kq * 4 + 2][m] = v.z;
            As[kq * 4 + 3][m] = v.w;
        }
        for (int i = tid; i < BK * BN / 4; i += NT) {
            int kr = i / (BN / 4);
            int cq = i % (BN / 4);
            *(float4*)&Bs[kr][cq * 4] =
                *(const float4*)&W[(size_t)(k0 + kr) * Ncols + col0 + cq * 4];
        }
        __syncthreads();

#pragma unroll
        for (int k = 0; k < BK; k++) {
            float a[TM], b[TN];
#pragma unroll
            for (int j = 0; j < TM; j += 4) {
                float4 t = *(const float4*)&As[k][ty * TM + j];
                a[j] = t.x; a[j + 1] = t.y; a[j + 2] = t.z; a[j + 3] = t.w;
            }
#pragma unroll
            for (int j = 0; j < TN; j += 4) {
                float4 t = *(const float4*)&Bs[k][tx * TN + j];
                b[j] = t.x; b[j + 1] = t.y; b[j + 2] = t.z; b[j + 3] = t.w;
            }
#pragma unroll
            for (int i = 0; i < TM; i++)
#pragma unroll
                for (int j = 0; j < TN; j++)
                    acc[i][j] = fmaf(a[i], b[j], acc[i][j]);
        }
        __syncthreads();
    }

#pragma unroll
    for (int i = 0; i < TM; i++) {
        int r = row0 + ty * TM + i;
        if (r < M) {
#pragma unroll
            for (int j = 0; j < TN; j += 4) {
                float4 v = make_float4(acc[i][j], acc[i][j + 1],
                                       acc[i][j + 2], acc[i][j + 3]);
                *(float4*)&Hout[(size_t)r * Ncols + col0 + tx * TN + j] = v;
            }
        }
    }
}

// ---------------------------------------------------------------------------
// CSR aggregation, 128-dim: one warp per dst node, registers accumulate.
// G[i,:] = b + dinv[i]^2 * H[i,:] + sum_e w_e * H[src_e,:]
// ---------------------------------------------------------------------------
__global__ void k_agg128(const float* __restrict__ H, float* __restrict__ G,
                         const int* __restrict__ csr_src,
                         const float* __restrict__ csr_w,
                         const int* __restrict__ off,
                         const float* __restrict__ dinv,
                         const float* __restrict__ bias) {
    int t = blockIdx.x * blockDim.x + threadIdx.x;
    int i = t >> 5;
    if (i >= NN) return;
    int lane = t & 31;

    float dv = dinv[i];
    float w0 = dv * dv;
    float4 acc = *(const float4*)&bias[lane * 4];
    float4 hs  = *(const float4*)&H[(size_t)i * 128 + lane * 4];
    acc.x = fmaf(hs.x, w0, acc.x);
    acc.y = fmaf(hs.y, w0, acc.y);
    acc.z = fmaf(hs.z, w0, acc.z);
    acc.w = fmaf(hs.w, w0, acc.w);

    int beg = off[i], end = off[i + 1];
    int j = beg;
    for (; j + 4 <= end; j += 4) {
        int s0 = csr_src[j],     s1 = csr_src[j + 1];
        int s2 = csr_src[j + 2], s3 = csr_src[j + 3];
        float w0_ = csr_w[j],     w1_ = csr_w[j + 1];
        float w2_ = csr_w[j + 2], w3_ = csr_w[j + 3];
        float4 v0 = *(const float4*)&H[(size_t)s0 * 128 + lane * 4];
        float4 v1 = *(const float4*)&H[(size_t)s1 * 128 + lane * 4];
        float4 v2 = *(const float4*)&H[(size_t)s2 * 128 + lane * 4];
        float4 v3 = *(const float4*)&H[(size_t)s3 * 128 + lane * 4];
        acc.x = fmaf(v0.x, w0_, acc.x); acc.y = fmaf(v0.y, w0_, acc.y);
        acc.z = fmaf(v0.z, w0_, acc.z); acc.w = fmaf(v0.w, w0_, acc.w);
        acc.x = fmaf(v1.x, w1_, acc.x); acc.y = fmaf(v1.y, w1_, acc.y);
        acc.z = fmaf(v1.z, w1_, acc.z); acc.w = fmaf(v1.w, w1_, acc.w);
        acc.x = fmaf(v2.x, w2_, acc.x); acc.y = fmaf(v2.y, w2_, acc.y);
        acc.z = fmaf(v2.z, w2_, acc.z); acc.w = fmaf(v2.w, w2_, acc.w);
        acc.x = fmaf(v3.x, w3_, acc.x); acc.y = fmaf(v3.y, w3_, acc.y);
        acc.z = fmaf(v3.z, w3_, acc.z); acc.w = fmaf(v3.w, w3_, acc.w);
    }
    for (; j < end; j++) {
        int   s = csr_src[j];
        float w = csr_w[j];
        float4 v = *(const float4*)&H[(size_t)s * 128 + lane * 4];
        acc.x = fmaf(v.x, w, acc.x); acc.y = fmaf(v.y, w, acc.y);
        acc.z = fmaf(v.z, w, acc.z); acc.w = fmaf(v.w, w, acc.w);
    }
    *(float4*)&G[(size_t)i * 128 + lane * 4] = acc;
}

// ---------------------------------------------------------------------------
// CSR aggregation, 32-dim + fused log-softmax: 8 lanes per node.
// ---------------------------------------------------------------------------
__global__ void k_agg32_lsm(const float* __restrict__ H, float* __restrict__ out,
                            const int* __restrict__ csr_src,
                            const float* __restrict__ csr_w,
                            const int* __restrict__ off,
                            const float* __restrict__ dinv,
                            const float* __restrict__ bias) {
    int t = blockIdx.x * blockDim.x + threadIdx.x;
    int i = t >> 3;
    if (i >= NN) return;
    int sub = t & 7;

    float dv = dinv[i];
    float w0 = dv * dv;
    float4 acc = *(const float4*)&bias[sub * 4];
    float4 hs  = *(const float4*)&H[(size_t)i * 32 + sub * 4];
    acc.x = fmaf(hs.x, w0, acc.x);
    acc.y = fmaf(hs.y, w0, acc.y);
    acc.z = fmaf(hs.z, w0, acc.z);
    acc.w = fmaf(hs.w, w0, acc.w);

    int beg = off[i], end = off[i + 1];
    int j = beg;
    for (; j + 2 <= end; j += 2) {
        int   s0 = csr_src[j], s1 = csr_src[j + 1];
        float w0_ = csr_w[j],  w1_ = csr_w[j + 1];
        float4 v0 = *(const float4*)&H[(size_t)s0 * 32 + sub * 4];
        float4 v1 = *(const float4*)&H[(size_t)s1 * 32 + sub * 4];
        acc.x = fmaf(v0.x, w0_, acc.x); acc.y = fmaf(v0.y, w0_, acc.y);
        acc.z = fmaf(v0.z, w0_, acc.z); acc.w = fmaf(v0.w, w0_, acc.w);
        acc.x = fmaf(v1.x, w1_, acc.x); acc.y = fmaf(v1.y, w1_, acc.y);
        acc.z = fmaf(v1.z, w1_, acc.z); acc.w = fmaf(v1.w, w1_, acc.w);
    }
    if (j < end) {
        int   s = csr_src[j];
        float w = csr_w[j];
        float4 v = *(const float4*)&H[(size_t)s * 32 + sub * 4];
        acc.x = fmaf(v.x, w, acc.x); acc.y = fmaf(v.y, w, acc.y);
        acc.z = fmaf(v.z, w, acc.z); acc.w = fmaf(v.w, w, acc.w);
    }

    // log-softmax over the node's 32 values (8-lane group, 4 each)
    unsigned m = __activemask();
    float mx = fmaxf(fmaxf(acc.x, acc.y), fmaxf(acc.z, acc.w));
#pragma unroll
    for (int o = 4; o > 0; o >>= 1)
        mx = fmaxf(mx, __shfl_xor_sync(m, mx, o));
    float ex = expf(acc.x - mx) + expf(acc.y - mx) +
               expf(acc.z - mx) + expf(acc.w - mx);
#pragma unroll
    for (int o = 4; o > 0; o >>= 1)
        ex += __shfl_xor_sync(m, ex, o);
    float ls = mx + logf(ex);

    float4 r;
    r.x = acc.x - ls; r.y = acc.y - ls; r.z = acc.z - ls; r.w = acc.w - ls;
    *(float4*)&out[(size_t)i * 32 + sub * 4] = r;
}

// ---------------------------------------------------------------------------
// Launch
// ---------------------------------------------------------------------------
extern "C" void kernel_launch(void* const* d_in, const int* in_sizes, int n_in,
                              void* d_out, int out_size) {
    const float*     x  = (const float*)d_in[0];
    const long long* ei = (const long long*)d_in[1];
    const float* W1 = (const float*)d_in[2];
    const float* b1 = (const float*)d_in[3];
    const float* W2 = (const float*)d_in[4];
    const float* b2 = (const float*)d_in[5];
    const float* W3 = (const float*)d_in[6];
    const float* b3 = (const float*)d_in[7];
    const float* W4 = (const float*)d_in[8];
    const float* b4 = (const float*)d_in[9];
    float* out = (float*)d_out;

    float *H, *G, *dinv, *csr_w;
    int *cnt, *off, *cursor, *tileSum, *tileBase, *csr_src;
    cudaGetSymbolAddress((void**)&H,        g_H);
    cudaGetSymbolAddress((void**)&G,        g_G);
    cudaGetSymbolAddress((void**)&dinv,     g_dinv);
    cudaGetSymbolAddress((void**)&cnt,      g_cnt);
    cudaGetSymbolAddress((void**)&off,      g_off);
    cudaGetSymbolAddress((void**)&cursor,   g_cursor);
    cudaGetSymbolAddress((void**)&tileSum,  g_tileSum);
    cudaGetSymbolAddress((void**)&tileBase, g_tileBase);
    cudaGetSymbolAddress((void**)&csr_src,  g_csr_src);
    cudaGetSymbolAddress((void**)&csr_w,    g_csr_w);

    const int TB = 256;
    const int nblk = NTILES;                   // node-grid
    const int eblk = (EE + TB - 1) / TB;       // edge-grid

    // --- CSR build ---
    k_detect_dtype<<<1, 32>>>(ei);
    k_zero_cnt<<<nblk, TB>>>(cnt);
    k_hist<<<eblk, TB>>>(ei, cnt);
    k_dinv<<<nblk, TB>>>(cnt, dinv);
    k_tile_sums<<<nblk, TB>>>(cnt, tileSum);
    k_scan_tilesums<<<1, 512>>>(tileSum, tileBase);
    k_scan_within<<<nblk, TB>>>(cnt, tileBase, off, cursor);
    k_fill<<<eblk, TB>>>(ei, dinv, cursor, csr_src, csr_w);

    const dim3 gemm_grid(1, (NN + 127) / 128);
    const int  agg128_blocks = (NN * 32 + TB - 1) / TB;
    const int  agg32_blocks  = (NN * 8 + TB - 1) / TB;

    // --- layer 1 ---
    k_gemm<128, 128, 8, 8, 8, false><<<gemm_grid, 256>>>(x, W1, H, NN, FD, FD);
    k_agg128<<<agg128_blocks, TB>>>(H, G, csr_src, csr_w, off, dinv, b1);

    // --- layer 2 ---
    k_gemm<128, 128, 8, 8, 8, true><<<gemm_grid, 256>>>(G, W2, H, NN, FD, FD);
    k_agg128<<<agg128_blocks, TB>>>(H, G, csr_src, csr_w, off, dinv, b2);

    // --- layer 3 ---
    k_gemm<128, 128, 8, 8, 8, true><<<gemm_grid, 256>>>(G, W3, H, NN, FD, FD);
    k_agg128<<<agg128_blocks, TB>>>(H, G, csr_src, csr_w, off, dinv, b3);

    // --- layer 4 + fused log-softmax ---
    k_gemm<128, 32, 8, 8, 4, true><<<gemm_grid, 128>>>(G, W4, H, NN, FD, CD);
    k_agg32_lsm<<<agg32_blocks, TB>>>(H, out, csr_src, csr_w, off, dinv, b4);
}

// round 6
// speedup vs baseline: 2.7572x; 1.1212x over previous
#include <cuda_runtime.h>
#include <cuda_bf16.h>
#include <math.h>
#include <stdint.h>

// Problem constants (fixed by the dataset)
#define NN 100000
#define EE 3200000
#define FD 128    // in/hidden feature dim
#define CD 32     // classes
#define NTILES ((NN + 255) / 256)   // 391

// SMEM row stride for bf16 tiles (128 data + 8 pad => conflict-free ldmatrix)
#define KS 136

// ---------------------------------------------------------------------------
// Scratch (static device globals: no allocation allowed in kernel_launch)
// ---------------------------------------------------------------------------
__device__ float g_H[NN * FD];            // GEMM output (fp32)      51.2 MB
__device__ __nv_bfloat16 g_Ahi[NN * FD];  // activation hi (bf16)    25.6 MB
__device__ __nv_bfloat16 g_Alo[NN * FD];  // activation lo (bf16)    25.6 MB
__device__ float g_dinv[NN];
__device__ int   g_cnt[NN];
__device__ int   g_off[NN + 1];
__device__ int   g_cursor[NN];
__device__ int   g_tileSum[NTILES];
__device__ int   g_tileBase[NTILES];
__device__ int   g_csr_src[EE];
__device__ float g_csr_w[EE];
__device__ int   g_is64;
__device__ __nv_bfloat16 g_Whi[3][FD * FD];   // transposed [N][K] bf16 hi
__device__ __nv_bfloat16 g_Wlo[3][FD * FD];   // transposed [N][K] bf16 lo
__device__ __nv_bfloat16 g_W4hi[CD * FD];
__device__ __nv_bfloat16 g_W4lo[CD * FD];

// ---------------------------------------------------------------------------
// Warp MMA helpers (baseline PTX, sm_80+: no 'a'-feature required)
// ---------------------------------------------------------------------------
__device__ __forceinline__ uint32_t smem_to_u32(const void* p) {
    uint32_t a;
    asm("{ .reg .u64 t; cvta.to.shared.u64 t, %1; cvt.u32.u64 %0, t; }"
        : "=r"(a) : "l"(p));
    return a;
}

__device__ __forceinline__ void ldsm_x4(uint32_t& r0, uint32_t& r1,
                                        uint32_t& r2, uint32_t& r3,
                                        uint32_t saddr) {
    asm volatile("ldmatrix.sync.aligned.m8n8.x4.shared.b16 {%0,%1,%2,%3}, [%4];"
                 : "=r"(r0), "=r"(r1), "=r"(r2), "=r"(r3) : "r"(saddr));
}

__device__ __forceinline__ void mma16816(float* c, const uint32_t* a,
                                         const uint32_t* b) {
    asm volatile(
        "mma.sync.aligned.m16n8k16.row.col.f32.bf16.bf16.f32 "
        "{%0,%1,%2,%3}, {%4,%5,%6,%7}, {%8,%9}, {%0,%1,%2,%3};"
        : "+f"(c[0]), "+f"(c[1]), "+f"(c[2]), "+f"(c[3])
        : "r"(a[0]), "r"(a[1]), "r"(a[2]), "r"(a[3]), "r"(b[0]), "r"(b[1]));
}

// ---------------------------------------------------------------------------
// Preprocessing (CSR build)
// ---------------------------------------------------------------------------
__global__ void k_detect_dtype(const long long* __restrict__ ei) {
    if (blockIdx.x == 0 && threadIdx.x == 0) {
        int ok = 1;
        for (int i = 0; i < 128; i++) {
            long long v = ei[i];
            if (v < 0 || v >= (long long)NN) { ok = 0; break; }
        }
        g_is64 = ok;
    }
}

__global__ void k_zero_cnt(int* __restrict__ cnt) {
    int i = blockIdx.x * blockDim.x + threadIdx.x;
    if (i < NN) cnt[i] = 0;
}

__global__ void k_hist(const long long* __restrict__ ei, int* __restrict__ cnt) {
    int e = blockIdx.x * blockDim.x + threadIdx.x;
    if (e >= EE) return;
    int d = g_is64 ? (int)ei[EE + e] : ((const int*)ei)[EE + e];
    atomicAdd(&cnt[d], 1);
}

__global__ void k_dinv(const int* __restrict__ cnt, float* __restrict__ dinv) {
    int i = blockIdx.x * blockDim.x + threadIdx.x;
    if (i < NN) dinv[i] = rsqrtf((float)(cnt[i] + 1));  // +1 self-loop
}

__global__ void k_tile_sums(const int* __restrict__ cnt, int* __restrict__ tileSum) {
    __shared__ int sh[256];
    int t = threadIdx.x;
    int i = blockIdx.x * 256 + t;
    sh[t] = (i < NN) ? cnt[i] : 0;
    __syncthreads();
#pragma unroll
    for (int s = 128; s > 0; s >>= 1) {
        if (t < s) sh[t] += sh[t + s];
        __syncthreads();
    }
    if (t == 0) tileSum[blockIdx.x] = sh[0];
}

__global__ void k_scan_tilesums(const int* __restrict__ tileSum,
                                int* __restrict__ tileBase) {
    __shared__ int sh[512];
    int t = threadIdx.x;
    int v = (t < NTILES) ? tileSum[t] : 0;
    sh[t] = v;
    __syncthreads();
#pragma unroll
    for (int o = 1; o < 512; o <<= 1) {
        int a = (t >= o) ? sh[t - o] : 0;
        __syncthreads();
        sh[t] += a;
        __syncthreads();
    }
    if (t < NTILES) tileBase[t] = sh[t] - v;   // exclusive
}

__global__ void k_scan_within(const int* __restrict__ cnt,
                              const int* __restrict__ tileBase,
                              int* __restrict__ off, int* __restrict__ cursor) {
    __shared__ int sh[256];
    int t = threadIdx.x;
    int i = blockIdx.x * 256 + t;
    int v = (i < NN) ? cnt[i] : 0;
    sh[t] = v;
    __syncthreads();
#pragma unroll
    for (int o = 1; o < 256; o <<= 1) {
        int a = (t >= o) ? sh[t - o] : 0;
        __syncthreads();
        sh[t] += a;
        __syncthreads();
    }
    int incl = sh[t];
    if (i < NN) {
        int ex = tileBase[blockIdx.x] + incl - v;
        off[i] = ex;
        cursor[i] = ex;
        if (i == NN - 1) off[NN] = tileBase[blockIdx.x] + incl;
    }
}

__global__ void k_fill(const long long* __restrict__ ei,
                       const float* __restrict__ dinv,
                       int* __restrict__ cursor,
                       int* __restrict__ csr_src, float* __restrict__ csr_w) {
    int e = blockIdx.x * blockDim.x + threadIdx.x;
    if (e >= EE) return;
    int s, d;
    if (g_is64) {
        s = (int)ei[e];
        d = (int)ei[EE + e];
    } else {
        const int* ei32 = (const int*)ei;
        s = ei32[e];
        d = ei32[EE + e];
    }
    int pos = atomicAdd(&cursor[d], 1);
    csr_src[pos] = s;
    csr_w[pos]   = dinv[s] * dinv[d];
}

// ---------------------------------------------------------------------------
// bf16 hi/lo splits
// ---------------------------------------------------------------------------
__device__ __forceinline__ void split2(float a, float b, uint32_t& h, uint32_t& l) {
    __nv_bfloat16 ha = __float2bfloat16(a);
    __nv_bfloat16 hb = __float2bfloat16(b);
    __nv_bfloat16 la = __float2bfloat16(a - __bfloat162float(ha));
    __nv_bfloat16 lb = __float2bfloat16(b - __bfloat162float(hb));
    __nv_bfloat162 hp = __halves2bfloat162(ha, hb);
    __nv_bfloat162 lp = __halves2bfloat162(la, lb);
    h = reinterpret_cast<uint32_t&>(hp);
    l = reinterpret_cast<uint32_t&>(lp);
}

__global__ void k_splitX(const float* __restrict__ x,
                         __nv_bfloat16* __restrict__ hi,
                         __nv_bfloat16* __restrict__ lo) {
    int idx = blockIdx.x * blockDim.x + threadIdx.x;   // per float4
    if (idx >= NN * FD / 4) return;
    float4 v = *(const float4*)(x + (size_t)idx * 4);
    uint2 hh, ll;
    split2(v.x, v.y, hh.x, ll.x);
    split2(v.z, v.w, hh.y, ll.y);
    *(uint2*)(hi + (size_t)idx * 4) = hh;
    *(uint2*)(lo + (size_t)idx * 4) = ll;
}

// Transposed weight split: out[n*128 + k] = split(W[k*Ncols + n])
__global__ void k_splitW(const float* __restrict__ W,
                         __nv_bfloat16* __restrict__ hi,
                         __nv_bfloat16* __restrict__ lo, int Ncols) {
    int idx = blockIdx.x * blockDim.x + threadIdx.x;
    if (idx >= Ncols * FD) return;
    int n = idx / FD, k = idx % FD;
    float v = W[(size_t)k * Ncols + n];
    __nv_bfloat16 h = __float2bfloat16(v);
    hi[idx] = h;
    lo[idx] = __float2bfloat16(v - __bfloat162float(h));
}

// ---------------------------------------------------------------------------
// Tensor-core GEMM (mma.sync bf16, 3-term split, fp32 accum)
// H[M, BN] = (Ahi+Alo)[M,128] @ (Bhi+Blo)[BN,128]^T
// One CTA per 128-row tile; 8 warps.
//   BN=128: warp grid 4(M)x2(N): each warp 32 rows x 64 cols  (MA=2, NA=8)
//   BN=32 : warp grid 8(M)x1(N): each warp 16 rows x 32 cols  (MA=1, NA=4)
// ---------------------------------------------------------------------------
template <int BN>
__global__ void __launch_bounds__(256, 1)
k_mma(const __nv_bfloat16* __restrict__ Ahi, const __nv_bfloat16* __restrict__ Alo,
      const __nv_bfloat16* __restrict__ Bhi, const __nv_bfloat16* __restrict__ Blo,
      float* __restrict__ H, int M) {
    constexpr int WM = (BN == 128) ? 4 : 8;        // warps along M
    constexpr int WN = 8 / WM;                     // warps along N
    constexpr int MA = 128 / (WM * 16);            // m16 atoms per warp
    constexpr int NA = (BN / WN) / 8;              // n8 atoms per warp

    extern __shared__ char smem[];
    const uint32_t sb  = smem_to_u32(smem);
    const uint32_t sAH = sb;
    const uint32_t sAL = sAH + 128 * KS * 2;
    const uint32_t sBH = sAL + 128 * KS * 2;
    const uint32_t sBL = sBH + BN * KS * 2;

    const int tid  = threadIdx.x;
    const int wid  = tid >> 5;
    const int lane = tid & 31;
    const int row0 = blockIdx.x * 128;
    const int wm   = wid % WM;
    const int wn   = wid / WM;
    const int rbase = wm * (128 / WM);             // warp row base in tile
    const int cbase = wn * (BN / WN);              // warp col base in tile

    // --- stage A tiles (zero-pad rows past M) and B tiles into SMEM ---
    int rows_valid = M - row0;
    if (rows_valid > 128) rows_valid = 128;
    {
        const __nv_bfloat16* Ah = Ahi + (size_t)row0 * 128;
        const __nv_bfloat16* Al = Alo + (size_t)row0 * 128;
        for (int idx = tid; idx < 128 * 16; idx += 256) {
            int row = idx >> 4, c = idx & 15;      // c: 8-bf16 chunk
            uint4 vh = make_uint4(0, 0, 0, 0), vl = vh;
            if (row < rows_valid) {
                vh = *(const uint4*)(Ah + (size_t)row * 128 + c * 8);
                vl = *(const uint4*)(Al + (size_t)row * 128 + c * 8);
            }
            uint32_t o = (uint32_t)(row * KS + c * 8) * 2;
            *(uint4*)(smem + (sAH - sb) + o) = vh;
            *(uint4*)(smem + (sAL - sb) + o) = vl;
        }
        for (int idx = tid; idx < BN * 16; idx += 256) {
            int row = idx >> 4, c = idx & 15;
            uint4 vh = *(const uint4*)(Bhi + (size_t)row * 128 + c * 8);
            uint4 vl = *(const uint4*)(Blo + (size_t)row * 128 + c * 8);
            uint32_t o = (uint32_t)(row * KS + c * 8) * 2;
            *(uint4*)(smem + (sBH - sb) + o) = vh;
            *(uint4*)(smem + (sBL - sb) + o) = vl;
        }
    }
    __syncthreads();

    float acc[MA][NA][4];
#pragma unroll
    for (int i = 0; i < MA; i++)
#pragma unroll
        for (int j = 0; j < NA; j++)
#pragma unroll
            for (int q = 0; q < 4; q++) acc[i][j][q] = 0.0f;

    // ldmatrix per-lane address components
    const int aq   = lane >> 3;                    // 0..3 quadrant
    const int aw   = lane & 7;
    const int arow = (aq & 1) * 8 + aw;            // row within 16-row tile
    const int acol = (aq >> 1) * 8;                // k offset 0/8
    const int brow = (aq >> 1) * 8 + aw;           // n offset within atom-pair
    const int bcol = (aq & 1) * 8;                 // k offset 0/8

#pragma unroll
    for (int ko = 0; ko < 8; ko++) {
        const int k0 = ko * 16;
        uint32_t ah[MA][4], al[MA][4];
#pragma unroll
        for (int ma = 0; ma < MA; ma++) {
            uint32_t off = (uint32_t)((rbase + ma * 16 + arow) * KS + k0 + acol) * 2;
            ldsm_x4(ah[ma][0], ah[ma][1], ah[ma][2], ah[ma][3], sAH + off);
            ldsm_x4(al[ma][0], al[ma][1], al[ma][2], al[ma][3], sAL + off);
        }
        uint32_t bh[NA][2], bl[NA][2];
#pragma unroll
        for (int nbp = 0; nbp < NA / 2; nbp++) {
            uint32_t off = (uint32_t)((cbase + nbp * 16 + brow) * KS + k0 + bcol) * 2;
            ldsm_x4(bh[nbp * 2][0], bh[nbp * 2][1],
                    bh[nbp * 2 + 1][0], bh[nbp * 2 + 1][1], sBH + off);
            ldsm_x4(bl[nbp * 2][0], bl[nbp * 2][1],
                    bl[nbp * 2 + 1][0], bl[nbp * 2 + 1][1], sBL + off);
        }
#pragma unroll
        for (int ma = 0; ma < MA; ma++)
#pragma unroll
            for (int na = 0; na < NA; na++) {
                mma16816(acc[ma][na], ah[ma], bh[na]);   // AhBh
                mma16816(acc[ma][na], ah[ma], bl[na]);   // AhBl
                mma16816(acc[ma][na], al[ma], bh[na]);   // AlBh
            }
    }

    // --- store accumulators ---
    const int crow = lane >> 2;                    // 0..7
    const int ccol = (lane & 3) * 2;
#pragma unroll
    for (int ma = 0; ma < MA; ma++) {
        int r0 = row0 + rbase + ma * 16 + crow;
        int r1 = r0 + 8;
        bool ok0 = r0 < M, ok1 = r1 < M;
#pragma unroll
        for (int na = 0; na < NA; na++) {
            int c = cbase + na * 8 + ccol;
            if (ok0) *(float2*)&H[(size_t)r0 * BN + c] =
                         make_float2(acc[ma][na][0], acc[ma][na][1]);
            if (ok1) *(float2*)&H[(size_t)r1 * BN + c] =
                         make_float2(acc[ma][na][2], acc[ma][na][3]);
        }
    }
}

// ---------------------------------------------------------------------------
// CSR aggregation, 128-dim: one warp per dst node.
// acc = b + dinv^2 * H[i] + sum w_e * H[src_e]; output = relu-split bf16 hi/lo
// ---------------------------------------------------------------------------
__global__ void k_agg128(const float* __restrict__ H,
                         __nv_bfloat16* __restrict__ Ghi,
                         __nv_bfloat16* __restrict__ Glo,
                         const int* __restrict__ csr_src,
                         const float* __restrict__ csr_w,
                         const int* __restrict__ off,
                         const float* __restrict__ dinv,
                         const float* __restrict__ bias) {
    int t = blockIdx.x * blockDim.x + threadIdx.x;
    int i = t >> 5;
    if (i >= NN) return;
    int lane = t & 31;

    float dv = dinv[i];
    float w0 = dv * dv;
    float4 acc = *(const float4*)&bias[lane * 4];
    float4 hs  = *(const float4*)&H[(size_t)i * 128 + lane * 4];
    acc.x = fmaf(hs.x, w0, acc.x);
    acc.y = fmaf(hs.y, w0, acc.y);
    acc.z = fmaf(hs.z, w0, acc.z);
    acc.w = fmaf(hs.w, w0, acc.w);

    int beg = off[i], end = off[i + 1];
    int j = beg;
    for (; j + 4 <= end; j += 4) {
        int s0 = csr_src[j],     s1 = csr_src[j + 1];
        int s2 = csr_src[j + 2], s3 = csr_src[j + 3];
        float w0_ = csr_w[j],     w1_ = csr_w[j + 1];
        float w2_ = csr_w[j + 2], w3_ = csr_w[j + 3];
        float4 v0 = *(const float4*)&H[(size_t)s0 * 128 + lane * 4];
        float4 v1 = *(const float4*)&H[(size_t)s1 * 128 + lane * 4];
        float4 v2 = *(const float4*)&H[(size_t)s2 * 128 + lane * 4];
        float4 v3 = *(const float4*)&H[(size_t)s3 * 128 + lane * 4];
        acc.x = fmaf(v0.x, w0_, acc.x); acc.y = fmaf(v0.y, w0_, acc.y);
        acc.z = fmaf(v0.z, w0_, acc.z); acc.w = fmaf(v0.w, w0_, acc.w);
        acc.x = fmaf(v1.x, w1_, acc.x); acc.y = fmaf(v1.y, w1_, acc.y);
        acc.z = fmaf(v1.z, w1_, acc.z); acc.w = fmaf(v1.w, w1_, acc.w);
        acc.x = fmaf(v2.x, w2_, acc.x); acc.y = fmaf(v2.y, w2_, acc.y);
        acc.z = fmaf(v2.z, w2_, acc.z); acc.w = fmaf(v2.w, w2_, acc.w);
        acc.x = fmaf(v3.x, w3_, acc.x); acc.y = fmaf(v3.y, w3_, acc.y);
        acc.z = fmaf(v3.z, w3_, acc.z); acc.w = fmaf(v3.w, w3_, acc.w);
    }
    for (; j < end; j++) {
        int   s = csr_src[j];
        float w = csr_w[j];
        float4 v = *(const float4*)&H[(size_t)s * 128 + lane * 4];
        acc.x = fmaf(v.x, w, acc.x); acc.y = fmaf(v.y, w, acc.y);
        acc.z = fmaf(v.z, w, acc.z); acc.w = fmaf(v.w, w, acc.w);
    }

    // ReLU + hi/lo bf16 split (next layer's GEMM input)
    float vx = fmaxf(acc.x, 0.f), vy = fmaxf(acc.y, 0.f);
    float vz = fmaxf(acc.z, 0.f), vw = fmaxf(acc.w, 0.f);
    uint2 hh, ll;
    split2(vx, vy, hh.x, ll.x);
    split2(vz, vw, hh.y, ll.y);
    *(uint2*)(Ghi + (size_t)i * 128 + lane * 4) = hh;
    *(uint2*)(Glo + (size_t)i * 128 + lane * 4) = ll;
}

// ---------------------------------------------------------------------------
// CSR aggregation, 32-dim + fused log-softmax: 8 lanes per node.
// ---------------------------------------------------------------------------
__global__ void k_agg32_lsm(const float* __restrict__ H, float* __restrict__ out,
                            const int* __restrict__ csr_src,
                            const float* __restrict__ csr_w,
                            const int* __restrict__ off,
                            const float* __restrict__ dinv,
                            const float* __restrict__ bias) {
    int t = blockIdx.x * blockDim.x + threadIdx.x;
    int i = t >> 3;
    if (i >= NN) return;
    int sub = t & 7;

    float dv = dinv[i];
    float w0 = dv * dv;
    float4 acc = *(const float4*)&bias[sub * 4];
    float4 hs  = *(const float4*)&H[(size_t)i * 32 + sub * 4];
    acc.x = fmaf(hs.x, w0, acc.x);
    acc.y = fmaf(hs.y, w0, acc.y);
    acc.z = fmaf(hs.z, w0, acc.z);
    acc.w = fmaf(hs.w, w0, acc.w);

    int beg = off[i], end = off[i + 1];
    int j = beg;
    for (; j + 2 <= end; j += 2) {
        int   s0 = csr_src[j], s1 = csr_src[j + 1];
        float w0_ = csr_w[j],  w1_ = csr_w[j + 1];
        float4 v0 = *(const float4*)&H[(size_t)s0 * 32 + sub * 4];
        float4 v1 = *(const float4*)&H[(size_t)s1 * 32 + sub * 4];
        acc.x = fmaf(v0.x, w0_, acc.x); acc.y = fmaf(v0.y, w0_, acc.y);
        acc.z = fmaf(v0.z, w0_, acc.z); acc.w = fmaf(v0.w, w0_, acc.w);
        acc.x = fmaf(v1.x, w1_, acc.x); acc.y = fmaf(v1.y, w1_, acc.y);
        acc.z = fmaf(v1.z, w1_, acc.z); acc.w = fmaf(v1.w, w1_, acc.w);
    }
    if (j < end) {
        int   s = csr_src[j];
        float w = csr_w[j];
        float4 v = *(const float4*)&H[(size_t)s * 32 + sub * 4];
        acc.x = fmaf(v.x, w, acc.x); acc.y = fmaf(v.y, w, acc.y);
        acc.z = fmaf(v.z, w, acc.z); acc.w = fmaf(v.w, w, acc.w);
    }

    unsigned m = __activemask();
    float mx = fmaxf(fmaxf(acc.x, acc.y), fmaxf(acc.z, acc.w));
#pragma unroll
    for (int o = 4; o > 0; o >>= 1)
        mx = fmaxf(mx, __shfl_xor_sync(m, mx, o));
    float ex = expf(acc.x - mx) + expf(acc.y - mx) +
               expf(acc.z - mx) + expf(acc.w - mx);
#pragma unroll
    for (int o = 4; o > 0; o >>= 1)
        ex += __shfl_xor_sync(m, ex, o);
    float ls = mx + logf(ex);

    float4 r;
    r.x = acc.x - ls; r.y = acc.y - ls; r.z = acc.z - ls; r.w = acc.w - ls;
    *(float4*)&out[(size_t)i * 32 + sub * 4] = r;
}

// ---------------------------------------------------------------------------
// Launch
// ---------------------------------------------------------------------------
extern "C" void kernel_launch(void* const* d_in, const int* in_sizes, int n_in,
                              void* d_out, int out_size) {
    const float*     x  = (const float*)d_in[0];
    const long long* ei = (const long long*)d_in[1];
    const float* W1 = (const float*)d_in[2];
    const float* b1 = (const float*)d_in[3];
    const float* W2 = (const float*)d_in[4];
    const float* b2 = (const float*)d_in[5];
    const float* W3 = (const float*)d_in[6];
    const float* b3 = (const float*)d_in[7];
    const float* W4 = (const float*)d_in[8];
    const float* b4 = (const float*)d_in[9];
    float* out = (float*)d_out;

    float *H, *dinv, *csr_w;
    __nv_bfloat16 *Ahi, *Alo, *Whi, *Wlo, *W4hi, *W4lo;
    int *cnt, *off, *cursor, *tileSum, *tileBase, *csr_src;
    cudaGetSymbolAddress((void**)&H,        g_H);
    cudaGetSymbolAddress((void**)&Ahi,      g_Ahi);
    cudaGetSymbolAddress((void**)&Alo,      g_Alo);
    cudaGetSymbolAddress((void**)&dinv,     g_dinv);
    cudaGetSymbolAddress((void**)&cnt,      g_cnt);
    cudaGetSymbolAddress((void**)&off,      g_off);
    cudaGetSymbolAddress((void**)&cursor,   g_cursor);
    cudaGetSymbolAddress((void**)&tileSum,  g_tileSum);
    cudaGetSymbolAddress((void**)&tileBase, g_tileBase);
    cudaGetSymbolAddress((void**)&csr_src,  g_csr_src);
    cudaGetSymbolAddress((void**)&csr_w,    g_csr_w);
    cudaGetSymbolAddress((void**)&Whi,      g_Whi);
    cudaGetSymbolAddress((void**)&Wlo,      g_Wlo);
    cudaGetSymbolAddress((void**)&W4hi,     g_W4hi);
    cudaGetSymbolAddress((void**)&W4lo,     g_W4lo);

    const int TB = 256;
    const int nblk = NTILES;
    const int eblk = (EE + TB - 1) / TB;

    // dynamic smem: (128 + 128 + BN + BN) rows * KS bf16
    const int SMEM128 = (128 + 128 + 128 + 128) * KS * 2;   // 139264
    const int SMEM32  = (128 + 128 + 32 + 32) * KS * 2;     // 87040
    cudaFuncSetAttribute((const void*)k_mma<128>,
                         cudaFuncAttributeMaxDynamicSharedMemorySize, SMEM128);
    cudaFuncSetAttribute((const void*)k_mma<32>,
                         cudaFuncAttributeMaxDynamicSharedMemorySize, SMEM32);

    // --- CSR build ---
    k_detect_dtype<<<1, 32>>>(ei);
    k_zero_cnt<<<nblk, TB>>>(cnt);
    k_hist<<<eblk, TB>>>(ei, cnt);
    k_dinv<<<nblk, TB>>>(cnt, dinv);
    k_tile_sums<<<nblk, TB>>>(cnt, tileSum);
    k_scan_tilesums<<<1, 512>>>(tileSum, tileBase);
    k_scan_within<<<nblk, TB>>>(cnt, tileBase, off, cursor);
    k_fill<<<eblk, TB>>>(ei, dinv, cursor, csr_src, csr_w);

    // --- splits ---
    k_splitX<<<(NN * FD / 4 + TB - 1) / TB, TB>>>(x, Ahi, Alo);
    k_splitW<<<(FD * FD + TB - 1) / TB, TB>>>(W1, Whi + 0 * FD * FD, Wlo + 0 * FD * FD, FD);
    k_splitW<<<(FD * FD + TB - 1) / TB, TB>>>(W2, Whi + 1 * FD * FD, Wlo + 1 * FD * FD, FD);
    k_splitW<<<(FD * FD + TB - 1) / TB, TB>>>(W3, Whi + 2 * FD * FD, Wlo + 2 * FD * FD, FD);
    k_splitW<<<(CD * FD + TB - 1) / TB, TB>>>(W4, W4hi, W4lo, CD);

    const int mma_grid = (NN + 127) / 128;   // 782
    const int agg128_blocks = (NN * 32 + TB - 1) / TB;
    const int agg32_blocks  = (NN * 8 + TB - 1) / TB;

    // --- layer 1 ---
    k_mma<128><<<mma_grid, 256, SMEM128>>>(Ahi, Alo, Whi + 0 * FD * FD, Wlo + 0 * FD * FD, H, NN);
    k_agg128<<<agg128_blocks, TB>>>(H, Ahi, Alo, csr_src, csr_w, off, dinv, b1);

    // --- layer 2 ---
    k_mma<128><<<mma_grid, 256, SMEM128>>>(Ahi, Alo, Whi + 1 * FD * FD, Wlo + 1 * FD * FD, H, NN);
    k_agg128<<<agg128_blocks, TB>>>(H, Ahi, Alo, csr_src, csr_w, off, dinv, b2);

    // --- layer 3 ---
    k_mma<128><<<mma_grid, 256, SMEM128>>>(Ahi, Alo, Whi + 2 * FD * FD, Wlo + 2 * FD * FD, H, NN);
    k_agg128<<<agg128_blocks, TB>>>(H, Ahi, Alo, csr_src, csr_w, off, dinv, b3);

    // --- layer 4 (32 classes) + fused log-softmax ---
    k_mma<32><<<mma_grid, 256, SMEM32>>>(Ahi, Alo, W4hi, W4lo, H, NN);
    k_agg32_lsm<<<agg32_blocks, TB>>>(H, out, csr_src, csr_w, off, dinv, b4);
}

// round 7
// speedup vs baseline: 3.0830x; 1.1181x over previous
#include <cuda_runtime.h>
#include <cuda_bf16.h>
#include <cuda_fp16.h>
#include <math.h>
#include <stdint.h>

// Problem constants (fixed by the dataset)
#define NN 100000
#define EE 3200000
#define FD 128    // in/hidden feature dim
#define CD 32     // classes
#define NTILES ((NN + 255) / 256)   // 391

// SMEM row stride for bf16 tiles (128 data + 8 pad => conflict-free ldmatrix)
#define KS 136

// ---------------------------------------------------------------------------
// Scratch (static device globals: no allocation allowed in kernel_launch)
// ---------------------------------------------------------------------------
__device__ __half g_H[NN * FD];           // GEMM output (fp16)      25.6 MB
__device__ __nv_bfloat16 g_Ahi[NN * FD];  // activation hi (bf16)    25.6 MB
__device__ __nv_bfloat16 g_Alo[NN * FD];  // activation lo (bf16)    25.6 MB
__device__ float g_dinv[NN];
__device__ int   g_cnt[NN];
__device__ int   g_off[NN + 1];
__device__ int   g_cursor[NN];
__device__ int   g_tileSum[NTILES];
__device__ int   g_tileBase[NTILES];
__device__ int2  g_csr[EE];               // (src, weight bits)      25.6 MB
__device__ int   g_is64;
__device__ __nv_bfloat16 g_Whi[3][FD * FD];   // transposed [N][K] bf16 hi
__device__ __nv_bfloat16 g_Wlo[3][FD * FD];   // transposed [N][K] bf16 lo
__device__ __nv_bfloat16 g_W4hi[CD * FD];
__device__ __nv_bfloat16 g_W4lo[CD * FD];

// ---------------------------------------------------------------------------
// Warp MMA helpers (baseline PTX, sm_80+: no 'a'-feature required)
// ---------------------------------------------------------------------------
__device__ __forceinline__ uint32_t smem_to_u32(const void* p) {
    uint32_t a;
    asm("{ .reg .u64 t; cvta.to.shared.u64 t, %1; cvt.u32.u64 %0, t; }"
        : "=r"(a) : "l"(p));
    return a;
}

__device__ __forceinline__ void ldsm_x4(uint32_t& r0, uint32_t& r1,
                                        uint32_t& r2, uint32_t& r3,
                                        uint32_t saddr) {
    asm volatile("ldmatrix.sync.aligned.m8n8.x4.shared.b16 {%0,%1,%2,%3}, [%4];"
                 : "=r"(r0), "=r"(r1), "=r"(r2), "=r"(r3) : "r"(saddr));
}

__device__ __forceinline__ void mma16816(float* c, const uint32_t* a,
                                         const uint32_t* b) {
    asm volatile(
        "mma.sync.aligned.m16n8k16.row.col.f32.bf16.bf16.f32 "
        "{%0,%1,%2,%3}, {%4,%5,%6,%7}, {%8,%9}, {%0,%1,%2,%3};"
        : "+f"(c[0]), "+f"(c[1]), "+f"(c[2]), "+f"(c[3])
        : "r"(a[0]), "r"(a[1]), "r"(a[2]), "r"(a[3]), "r"(b[0]), "r"(b[1]));
}

// ---------------------------------------------------------------------------
// Preprocessing (CSR build)
// ---------------------------------------------------------------------------
__global__ void k_detect_dtype(const long long* __restrict__ ei) {
    if (blockIdx.x == 0 && threadIdx.x == 0) {
        int ok = 1;
        for (int i = 0; i < 128; i++) {
            long long v = ei[i];
            if (v < 0 || v >= (long long)NN) { ok = 0; break; }
        }
        g_is64 = ok;
    }
}

__global__ void k_zero_cnt(int* __restrict__ cnt) {
    int i = blockIdx.x * blockDim.x + threadIdx.x;
    if (i < NN) cnt[i] = 0;
}

__global__ void k_hist(const long long* __restrict__ ei, int* __restrict__ cnt) {
    int e = blockIdx.x * blockDim.x + threadIdx.x;
    if (e >= EE) return;
    int d = g_is64 ? (int)ei[EE + e] : ((const int*)ei)[EE + e];
    atomicAdd(&cnt[d], 1);
}

__global__ void k_dinv(const int* __restrict__ cnt, float* __restrict__ dinv) {
    int i = blockIdx.x * blockDim.x + threadIdx.x;
    if (i < NN) dinv[i] = rsqrtf((float)(cnt[i] + 1));  // +1 self-loop
}

__global__ void k_tile_sums(const int* __restrict__ cnt, int* __restrict__ tileSum) {
    __shared__ int sh[256];
    int t = threadIdx.x;
    int i = blockIdx.x * 256 + t;
    sh[t] = (i < NN) ? cnt[i] : 0;
    __syncthreads();
#pragma unroll
    for (int s = 128; s > 0; s >>= 1) {
        if (t < s) sh[t] += sh[t + s];
        __syncthreads();
    }
    if (t == 0) tileSum[blockIdx.x] = sh[0];
}

__global__ void k_scan_tilesums(const int* __restrict__ tileSum,
                                int* __restrict__ tileBase) {
    __shared__ int sh[512];
    int t = threadIdx.x;
    int v = (t < NTILES) ? tileSum[t] : 0;
    sh[t] = v;
    __syncthreads();
#pragma unroll
    for (int o = 1; o < 512; o <<= 1) {
        int a = (t >= o) ? sh[t - o] : 0;
        __syncthreads();
        sh[t] += a;
        __syncthreads();
    }
    if (t < NTILES) tileBase[t] = sh[t] - v;   // exclusive
}

__global__ void k_scan_within(const int* __restrict__ cnt,
                              const int* __restrict__ tileBase,
                              int* __restrict__ off, int* __restrict__ cursor) {
    __shared__ int sh[256];
    int t = threadIdx.x;
    int i = blockIdx.x * 256 + t;
    int v = (i < NN) ? cnt[i] : 0;
    sh[t] = v;
    __syncthreads();
#pragma unroll
    for (int o = 1; o < 256; o <<= 1) {
        int a = (t >= o) ? sh[t - o] : 0;
        __syncthreads();
        sh[t] += a;
        __syncthreads();
    }
    int incl = sh[t];
    if (i < NN) {
        int ex = tileBase[blockIdx.x] + incl - v;
        off[i] = ex;
        cursor[i] = ex;
        if (i == NN - 1) off[NN] = tileBase[blockIdx.x] + incl;
    }
}

__global__ void k_fill(const long long* __restrict__ ei,
                       const float* __restrict__ dinv,
                       int* __restrict__ cursor,
                       int2* __restrict__ csr) {
    int e = blockIdx.x * blockDim.x + threadIdx.x;
    if (e >= EE) return;
    int s, d;
    if (g_is64) {
        s = (int)ei[e];
        d = (int)ei[EE + e];
    } else {
        const int* ei32 = (const int*)ei;
        s = ei32[e];
        d = ei32[EE + e];
    }
    int pos = atomicAdd(&cursor[d], 1);
    csr[pos] = make_int2(s, __float_as_int(dinv[s] * dinv[d]));
}

// ---------------------------------------------------------------------------
// bf16 hi/lo splits
// ---------------------------------------------------------------------------
__device__ __forceinline__ void split2(float a, float b, uint32_t& h, uint32_t& l) {
    __nv_bfloat16 ha = __float2bfloat16(a);
    __nv_bfloat16 hb = __float2bfloat16(b);
    __nv_bfloat16 la = __float2bfloat16(a - __bfloat162float(ha));
    __nv_bfloat16 lb = __float2bfloat16(b - __bfloat162float(hb));
    __nv_bfloat162 hp = __halves2bfloat162(ha, hb);
    __nv_bfloat162 lp = __halves2bfloat162(la, lb);
    h = reinterpret_cast<uint32_t&>(hp);
    l = reinterpret_cast<uint32_t&>(lp);
}

__global__ void k_splitX(const float* __restrict__ x,
                         __nv_bfloat16* __restrict__ hi,
                         __nv_bfloat16* __restrict__ lo) {
    int idx = blockIdx.x * blockDim.x + threadIdx.x;   // per float4
    if (idx >= NN * FD / 4) return;
    float4 v = *(const float4*)(x + (size_t)idx * 4);
    uint2 hh, ll;
    split2(v.x, v.y, hh.x, ll.x);
    split2(v.z, v.w, hh.y, ll.y);
    *(uint2*)(hi + (size_t)idx * 4) = hh;
    *(uint2*)(lo + (size_t)idx * 4) = ll;
}

// Transposed weight split: out[n*128 + k] = split(W[k*Ncols + n])
__global__ void k_splitW(const float* __restrict__ W,
                         __nv_bfloat16* __restrict__ hi,
                         __nv_bfloat16* __restrict__ lo, int Ncols) {
    int idx = blockIdx.x * blockDim.x + threadIdx.x;
    if (idx >= Ncols * FD) return;
    int n = idx / FD, k = idx % FD;
    float v = W[(size_t)k * Ncols + n];
    __nv_bfloat16 h = __float2bfloat16(v);
    hi[idx] = h;
    lo[idx] = __float2bfloat16(v - __bfloat162float(h));
}

// ---------------------------------------------------------------------------
// Tensor-core GEMM (mma.sync bf16, 3-term split, fp32 accum, fp16 output)
// H[M, BN] = (Ahi+Alo)[M,128] @ (Bhi+Blo)[BN,128]^T
// One CTA per 128-row tile; 8 warps.
// ---------------------------------------------------------------------------
template <int BN>
__global__ void __launch_bounds__(256, 1)
k_mma(const __nv_bfloat16* __restrict__ Ahi, const __nv_bfloat16* __restrict__ Alo,
      const __nv_bfloat16* __restrict__ Bhi, const __nv_bfloat16* __restrict__ Blo,
      __half* __restrict__ H, int M) {
    constexpr int WM = (BN == 128) ? 4 : 8;        // warps along M
    constexpr int WN = 8 / WM;                     // warps along N
    constexpr int MA = 128 / (WM * 16);            // m16 atoms per warp
    constexpr int NA = (BN / WN) / 8;              // n8 atoms per warp

    extern __shared__ char smem[];
    const uint32_t sb  = smem_to_u32(smem);
    const uint32_t sAH = sb;
    const uint32_t sAL = sAH + 128 * KS * 2;
    const uint32_t sBH = sAL + 128 * KS * 2;
    const uint32_t sBL = sBH + BN * KS * 2;

    const int tid  = threadIdx.x;
    const int wid  = tid >> 5;
    const int lane = tid & 31;
    const int row0 = blockIdx.x * 128;
    const int wm   = wid % WM;
    const int wn   = wid / WM;
    const int rbase = wm * (128 / WM);             // warp row base in tile
    const int cbase = wn * (BN / WN);              // warp col base in tile

    // --- stage A tiles (zero-pad rows past M) and B tiles into SMEM ---
    int rows_valid = M - row0;
    if (rows_valid > 128) rows_valid = 128;
    {
        const __nv_bfloat16* Ah = Ahi + (size_t)row0 * 128;
        const __nv_bfloat16* Al = Alo + (size_t)row0 * 128;
        for (int idx = tid; idx < 128 * 16; idx += 256) {
            int row = idx >> 4, c = idx & 15;      // c: 8-bf16 chunk
            uint4 vh = make_uint4(0, 0, 0, 0), vl = vh;
            if (row < rows_valid) {
                vh = *(const uint4*)(Ah + (size_t)row * 128 + c * 8);
                vl = *(const uint4*)(Al + (size_t)row * 128 + c * 8);
            }
            uint32_t o = (uint32_t)(row * KS + c * 8) * 2;
            *(uint4*)(smem + (sAH - sb) + o) = vh;
            *(uint4*)(smem + (sAL - sb) + o) = vl;
        }
        for (int idx = tid; idx < BN * 16; idx += 256) {
            int row = idx >> 4, c = idx & 15;
            uint4 vh = *(const uint4*)(Bhi + (size_t)row * 128 + c * 8);
            uint4 vl = *(const uint4*)(Blo + (size_t)row * 128 + c * 8);
            uint32_t o = (uint32_t)(row * KS + c * 8) * 2;
            *(uint4*)(smem + (sBH - sb) + o) = vh;
            *(uint4*)(smem + (sBL - sb) + o) = vl;
        }
    }
    __syncthreads();

    float acc[MA][NA][4];
#pragma unroll
    for (int i = 0; i < MA; i++)
#pragma unroll
        for (int j = 0; j < NA; j++)
#pragma unroll
            for (int q = 0; q < 4; q++) acc[i][j][q] = 0.0f;

    // ldmatrix per-lane address components
    const int aq   = lane >> 3;                    // 0..3 quadrant
    const int aw   = lane & 7;
    const int arow = (aq & 1) * 8 + aw;            // row within 16-row tile
    const int acol = (aq >> 1) * 8;                // k offset 0/8
    const int brow = (aq >> 1) * 8 + aw;           // n offset within atom-pair
    const int bcol = (aq & 1) * 8;                 // k offset 0/8

#pragma unroll
    for (int ko = 0; ko < 8; ko++) {
        const int k0 = ko * 16;
        uint32_t ah[MA][4], al[MA][4];
#pragma unroll
        for (int ma = 0; ma < MA; ma++) {
            uint32_t off = (uint32_t)((rbase + ma * 16 + arow) * KS + k0 + acol) * 2;
            ldsm_x4(ah[ma][0], ah[ma][1], ah[ma][2], ah[ma][3], sAH + off);
            ldsm_x4(al[ma][0], al[ma][1], al[ma][2], al[ma][3], sAL + off);
        }
        uint32_t bh[NA][2], bl[NA][2];
#pragma unroll
        for (int nbp = 0; nbp < NA / 2; nbp++) {
            uint32_t off = (uint32_t)((cbase + nbp * 16 + brow) * KS + k0 + bcol) * 2;
            ldsm_x4(bh[nbp * 2][0], bh[nbp * 2][1],
                    bh[nbp * 2 + 1][0], bh[nbp * 2 + 1][1], sBH + off);
            ldsm_x4(bl[nbp * 2][0], bl[nbp * 2][1],
                    bl[nbp * 2 + 1][0], bl[nbp * 2 + 1][1], sBL + off);
        }
#pragma unroll
        for (int ma = 0; ma < MA; ma++)
#pragma unroll
            for (int na = 0; na < NA; na++) {
                mma16816(acc[ma][na], ah[ma], bh[na]);   // AhBh
                mma16816(acc[ma][na], ah[ma], bl[na]);   // AhBl
                mma16816(acc[ma][na], al[ma], bh[na]);   // AlBh
            }
    }

    // --- store accumulators as fp16 ---
    const int crow = lane >> 2;                    // 0..7
    const int ccol = (lane & 3) * 2;
#pragma unroll
    for (int ma = 0; ma < MA; ma++) {
        int r0 = row0 + rbase + ma * 16 + crow;
        int r1 = r0 + 8;
        bool ok0 = r0 < M, ok1 = r1 < M;
#pragma unroll
        for (int na = 0; na < NA; na++) {
            int c = cbase + na * 8 + ccol;
            if (ok0) *(__half2*)&H[(size_t)r0 * BN + c] =
                         __floats2half2_rn(acc[ma][na][0], acc[ma][na][1]);
            if (ok1) *(__half2*)&H[(size_t)r1 * BN + c] =
                         __floats2half2_rn(acc[ma][na][2], acc[ma][na][3]);
        }
    }
}

// ---------------------------------------------------------------------------
// CSR aggregation, 128-dim: one warp per dst node, fp16 gather, fp32 accum.
// acc = b + dinv^2 * H[i] + sum w_e * H[src_e]; output = relu-split bf16 hi/lo
// ---------------------------------------------------------------------------
__device__ __forceinline__ void acc_h4(float4& acc, float w, uint2 raw) {
    __half2 p0 = reinterpret_cast<__half2&>(raw.x);
    __half2 p1 = reinterpret_cast<__half2&>(raw.y);
    float2 f0 = __half22float2(p0);
    float2 f1 = __half22float2(p1);
    acc.x = fmaf(f0.x, w, acc.x);
    acc.y = fmaf(f0.y, w, acc.y);
    acc.z = fmaf(f1.x, w, acc.z);
    acc.w = fmaf(f1.y, w, acc.w);
}

__global__ void k_agg128(const __half* __restrict__ H,
                         __nv_bfloat16* __restrict__ Ghi,
                         __nv_bfloat16* __restrict__ Glo,
                         const int2* __restrict__ csr,
                         const int* __restrict__ off,
                         const float* __restrict__ dinv,
                         const float* __restrict__ bias) {
    int t = blockIdx.x * blockDim.x + threadIdx.x;
    int i = t >> 5;
    if (i >= NN) return;
    int lane = t & 31;

    float dv = dinv[i];
    float w0 = dv * dv;
    float4 acc = *(const float4*)&bias[lane * 4];
    acc_h4(acc, w0, *(const uint2*)(H + (size_t)i * 128 + lane * 4));

    int beg = off[i], end = off[i + 1];
    int j = beg;
    for (; j + 4 <= end; j += 4) {
        int2 e0 = csr[j],     e1 = csr[j + 1];
        int2 e2 = csr[j + 2], e3 = csr[j + 3];
        uint2 r0 = *(const uint2*)(H + (size_t)e0.x * 128 + lane * 4);
        uint2 r1 = *(const uint2*)(H + (size_t)e1.x * 128 + lane * 4);
        uint2 r2 = *(const uint2*)(H + (size_t)e2.x * 128 + lane * 4);
        uint2 r3 = *(const uint2*)(H + (size_t)e3.x * 128 + lane * 4);
        acc_h4(acc, __int_as_float(e0.y), r0);
        acc_h4(acc, __int_as_float(e1.y), r1);
        acc_h4(acc, __int_as_float(e2.y), r2);
        acc_h4(acc, __int_as_float(e3.y), r3);
    }
    for (; j < end; j++) {
        int2 e = csr[j];
        acc_h4(acc, __int_as_float(e.y),
               *(const uint2*)(H + (size_t)e.x * 128 + lane * 4));
    }

    // ReLU + hi/lo bf16 split (next layer's GEMM input)
    float vx = fmaxf(acc.x, 0.f), vy = fmaxf(acc.y, 0.f);
    float vz = fmaxf(acc.z, 0.f), vw = fmaxf(acc.w, 0.f);
    uint2 hh, ll;
    split2(vx, vy, hh.x, ll.x);
    split2(vz, vw, hh.y, ll.y);
    *(uint2*)(Ghi + (size_t)i * 128 + lane * 4) = hh;
    *(uint2*)(Glo + (size_t)i * 128 + lane * 4) = ll;
}

// ---------------------------------------------------------------------------
// CSR aggregation, 32-dim + fused log-softmax: 8 lanes per node, fp16 gather.
// ---------------------------------------------------------------------------
__global__ void k_agg32_lsm(const __half* __restrict__ H, float* __restrict__ out,
                            const int2* __restrict__ csr,
                            const int* __restrict__ off,
                            const float* __restrict__ dinv,
                            const float* __restrict__ bias) {
    int t = blockIdx.x * blockDim.x + threadIdx.x;
    int i = t >> 3;
    if (i >= NN) return;
    int sub = t & 7;

    float dv = dinv[i];
    float w0 = dv * dv;
    float4 acc = *(const float4*)&bias[sub * 4];
    acc_h4(acc, w0, *(const uint2*)(H + (size_t)i * 32 + sub * 4));

    int beg = off[i], end = off[i + 1];
    int j = beg;
    for (; j + 2 <= end; j += 2) {
        int2 e0 = csr[j], e1 = csr[j + 1];
        uint2 r0 = *(const uint2*)(H + (size_t)e0.x * 32 + sub * 4);
        uint2 r1 = *(const uint2*)(H + (size_t)e1.x * 32 + sub * 4);
        acc_h4(acc, __int_as_float(e0.y), r0);
        acc_h4(acc, __int_as_float(e1.y), r1);
    }
    if (j < end) {
        int2 e = csr[j];
        acc_h4(acc, __int_as_float(e.y),
               *(const uint2*)(H + (size_t)e.x * 32 + sub * 4));
    }

    unsigned m = __activemask();
    float mx = fmaxf(fmaxf(acc.x, acc.y), fmaxf(acc.z, acc.w));
#pragma unroll
    for (int o = 4; o > 0; o >>= 1)
        mx = fmaxf(mx, __shfl_xor_sync(m, mx, o));
    float ex = expf(acc.x - mx) + expf(acc.y - mx) +
               expf(acc.z - mx) + expf(acc.w - mx);
#pragma unroll
    for (int o = 4; o > 0; o >>= 1)
        ex += __shfl_xor_sync(m, ex, o);
    float ls = mx + logf(ex);

    float4 r;
    r.x = acc.x - ls; r.y = acc.y - ls; r.z = acc.z - ls; r.w = acc.w - ls;
    *(float4*)&out[(size_t)i * 32 + sub * 4] = r;
}

// ---------------------------------------------------------------------------
// Launch
// ---------------------------------------------------------------------------
extern "C" void kernel_launch(void* const* d_in, const int* in_sizes, int n_in,
                              void* d_out, int out_size) {
    const float*     x  = (const float*)d_in[0];
    const long long* ei = (const long long*)d_in[1];
    const float* W1 = (const float*)d_in[2];
    const float* b1 = (const float*)d_in[3];
    const float* W2 = (const float*)d_in[4];
    const float* b2 = (const float*)d_in[5];
    const float* W3 = (const float*)d_in[6];
    const float* b3 = (const float*)d_in[7];
    const float* W4 = (const float*)d_in[8];
    const float* b4 = (const float*)d_in[9];
    float* out = (float*)d_out;

    __half* H;
    float *dinv;
    __nv_bfloat16 *Ahi, *Alo, *Whi, *Wlo, *W4hi, *W4lo;
    int *cnt, *off, *cursor, *tileSum, *tileBase;
    int2* csr;
    cudaGetSymbolAddress((void**)&H,        g_H);
    cudaGetSymbolAddress((void**)&Ahi,      g_Ahi);
    cudaGetSymbolAddress((void**)&Alo,      g_Alo);
    cudaGetSymbolAddress((void**)&dinv,     g_dinv);
    cudaGetSymbolAddress((void**)&cnt,      g_cnt);
    cudaGetSymbolAddress((void**)&off,      g_off);
    cudaGetSymbolAddress((void**)&cursor,   g_cursor);
    cudaGetSymbolAddress((void**)&tileSum,  g_tileSum);
    cudaGetSymbolAddress((void**)&tileBase, g_tileBase);
    cudaGetSymbolAddress((void**)&csr,      g_csr);
    cudaGetSymbolAddress((void**)&Whi,      g_Whi);
    cudaGetSymbolAddress((void**)&Wlo,      g_Wlo);
    cudaGetSymbolAddress((void**)&W4hi,     g_W4hi);
    cudaGetSymbolAddress((void**)&W4lo,     g_W4lo);

    const int TB = 256;
    const int nblk = NTILES;
    const int eblk = (EE + TB - 1) / TB;

    // dynamic smem: (128 + 128 + BN + BN) rows * KS bf16
    const int SMEM128 = (128 + 128 + 128 + 128) * KS * 2;   // 139264
    const int SMEM32  = (128 + 128 + 32 + 32) * KS * 2;     // 87040
    cudaFuncSetAttribute((const void*)k_mma<128>,
                         cudaFuncAttributeMaxDynamicSharedMemorySize, SMEM128);
    cudaFuncSetAttribute((const void*)k_mma<32>,
                         cudaFuncAttributeMaxDynamicSharedMemorySize, SMEM32);

    // --- CSR build ---
    k_detect_dtype<<<1, 32>>>(ei);
    k_zero_cnt<<<nblk, TB>>>(cnt);
    k_hist<<<eblk, TB>>>(ei, cnt);
    k_dinv<<<nblk, TB>>>(cnt, dinv);
    k_tile_sums<<<nblk, TB>>>(cnt, tileSum);
    k_scan_tilesums<<<1, 512>>>(tileSum, tileBase);
    k_scan_within<<<nblk, TB>>>(cnt, tileBase, off, cursor);
    k_fill<<<eblk, TB>>>(ei, dinv, cursor, csr);

    // --- splits ---
    k_splitX<<<(NN * FD / 4 + TB - 1) / TB, TB>>>(x, Ahi, Alo);
    k_splitW<<<(FD * FD + TB - 1) / TB, TB>>>(W1, Whi + 0 * FD * FD, Wlo + 0 * FD * FD, FD);
    k_splitW<<<(FD * FD + TB - 1) / TB, TB>>>(W2, Whi + 1 * FD * FD, Wlo + 1 * FD * FD, FD);
    k_splitW<<<(FD * FD + TB - 1) / TB, TB>>>(W3, Whi + 2 * FD * FD, Wlo + 2 * FD * FD, FD);
    k_splitW<<<(CD * FD + TB - 1) / TB, TB>>>(W4, W4hi, W4lo, CD);

    const int mma_grid = (NN + 127) / 128;   // 782
    const int agg128_blocks = (NN * 32 + TB - 1) / TB;
    const int agg32_blocks  = (NN * 8 + TB - 1) / TB;

    // --- layer 1 ---
    k_mma<128><<<mma_grid, 256, SMEM128>>>(Ahi, Alo, Whi + 0 * FD * FD, Wlo + 0 * FD * FD, H, NN);
    k_agg128<<<agg128_blocks, TB>>>(H, Ahi, Alo, csr, off, dinv, b1);

    // --- layer 2 ---
    k_mma<128><<<mma_grid, 256, SMEM128>>>(Ahi, Alo, Whi + 1 * FD * FD, Wlo + 1 * FD * FD, H, NN);
    k_agg128<<<agg128_blocks, TB>>>(H, Ahi, Alo, csr, off, dinv, b2);

    // --- layer 3 ---
    k_mma<128><<<mma_grid, 256, SMEM128>>>(Ahi, Alo, Whi + 2 * FD * FD, Wlo + 2 * FD * FD, H, NN);
    k_agg128<<<agg128_blocks, TB>>>(H, Ahi, Alo, csr, off, dinv, b3);

    // --- layer 4 (32 classes) + fused log-softmax ---
    k_mma<32><<<mma_grid, 256, SMEM32>>>(Ahi, Alo, W4hi, W4lo, H, NN);
    k_agg32_lsm<<<agg32_blocks, TB>>>(H, out, csr, off, dinv, b4);
}

// round 8
// speedup vs baseline: 3.8875x; 1.2609x over previous
#include <cuda_runtime.h>
#include <cuda_bf16.h>
#include <cuda_fp16.h>
#include <math.h>
#include <stdint.h>

// Problem constants (fixed by the dataset)
#define NN 100000
#define EE 3200000
#define FD 128    // in/hidden feature dim
#define CD 32     // classes
#define NTILES ((NN + 255) / 256)   // 391

// SMEM row stride for bf16 tiles (128 data + 8 pad => conflict-free ldmatrix)
#define KS 136

// ---------------------------------------------------------------------------
// Scratch (static device globals: no allocation allowed in kernel_launch)
// ---------------------------------------------------------------------------
__device__ __half g_H[NN * FD];           // GEMM output (fp16)      25.6 MB
__device__ __nv_bfloat16 g_Ahi[NN * FD];  // activation hi (bf16)    25.6 MB
__device__ __nv_bfloat16 g_Alo[NN * FD];  // activation lo (bf16)    25.6 MB
__device__ float g_dinv[NN];
__device__ int   g_cnt[NN];
__device__ int   g_off[NN + 1];
__device__ int   g_cursor[NN];
__device__ int   g_tileSum[NTILES];
__device__ int   g_tileBase[NTILES];
__device__ int2  g_csr[EE];               // (src, weight bits)      25.6 MB
__device__ int   g_is64;
__device__ __nv_bfloat16 g_Whi[3][FD * FD];   // transposed [N][K] bf16 hi
__device__ __nv_bfloat16 g_Wlo[3][FD * FD];   // transposed [N][K] bf16 lo
__device__ __nv_bfloat16 g_W4hi[CD * FD];
__device__ __nv_bfloat16 g_W4lo[CD * FD];

// ---------------------------------------------------------------------------
// Warp MMA + cp.async helpers (baseline PTX, sm_80+: no 'a'-feature required)
// ---------------------------------------------------------------------------
__device__ __forceinline__ uint32_t smem_to_u32(const void* p) {
    uint32_t a;
    asm("{ .reg .u64 t; cvta.to.shared.u64 t, %1; cvt.u32.u64 %0, t; }"
        : "=r"(a) : "l"(p));
    return a;
}

__device__ __forceinline__ void ldsm_x4(uint32_t& r0, uint32_t& r1,
                                        uint32_t& r2, uint32_t& r3,
                                        uint32_t saddr) {
    asm volatile("ldmatrix.sync.aligned.m8n8.x4.shared.b16 {%0,%1,%2,%3}, [%4];"
                 : "=r"(r0), "=r"(r1), "=r"(r2), "=r"(r3) : "r"(saddr));
}

__device__ __forceinline__ void mma16816(float* c, const uint32_t* a,
                                         const uint32_t* b) {
    asm volatile(
        "mma.sync.aligned.m16n8k16.row.col.f32.bf16.bf16.f32 "
        "{%0,%1,%2,%3}, {%4,%5,%6,%7}, {%8,%9}, {%0,%1,%2,%3};"
        : "+f"(c[0]), "+f"(c[1]), "+f"(c[2]), "+f"(c[3])
        : "r"(a[0]), "r"(a[1]), "r"(a[2]), "r"(a[3]), "r"(b[0]), "r"(b[1]));
}

__device__ __forceinline__ void cp_async16(uint32_t sdst, const void* gsrc, int sz) {
    asm volatile("cp.async.cg.shared.global [%0], [%1], 16, %2;"
                 :: "r"(sdst), "l"(gsrc), "r"(sz) : "memory");
}
#define CP_COMMIT() asm volatile("cp.async.commit_group;" ::: "memory")
#define CP_WAIT(n)  asm volatile("cp.async.wait_group %0;" :: "n"(n) : "memory")

// ---------------------------------------------------------------------------
// Preprocessing (CSR build)
// ---------------------------------------------------------------------------
__global__ void k_detect_dtype(const long long* __restrict__ ei) {
    if (blockIdx.x == 0 && threadIdx.x == 0) {
        int ok = 1;
        for (int i = 0; i < 128; i++) {
            long long v = ei[i];
            if (v < 0 || v >= (long long)NN) { ok = 0; break; }
        }
        g_is64 = ok;
    }
}

__global__ void k_zero_cnt(int* __restrict__ cnt) {
    int i = blockIdx.x * blockDim.x + threadIdx.x;
    if (i < NN) cnt[i] = 0;
}

__global__ void k_hist(const long long* __restrict__ ei, int* __restrict__ cnt) {
    int e = blockIdx.x * blockDim.x + threadIdx.x;
    if (e >= EE) return;
    int d = g_is64 ? (int)ei[EE + e] : ((const int*)ei)[EE + e];
    atomicAdd(&cnt[d], 1);
}

__global__ void k_dinv(const int* __restrict__ cnt, float* __restrict__ dinv) {
    int i = blockIdx.x * blockDim.x + threadIdx.x;
    if (i < NN) dinv[i] = rsqrtf((float)(cnt[i] + 1));  // +1 self-loop
}

__global__ void k_tile_sums(const int* __restrict__ cnt, int* __restrict__ tileSum) {
    __shared__ int sh[256];
    int t = threadIdx.x;
    int i = blockIdx.x * 256 + t;
    sh[t] = (i < NN) ? cnt[i] : 0;
    __syncthreads();
#pragma unroll
    for (int s = 128; s > 0; s >>= 1) {
        if (t < s) sh[t] += sh[t + s];
        __syncthreads();
    }
    if (t == 0) tileSum[blockIdx.x] = sh[0];
}

__global__ void k_scan_tilesums(const int* __restrict__ tileSum,
                                int* __restrict__ tileBase) {
    __shared__ int sh[512];
    int t = threadIdx.x;
    int v = (t < NTILES) ? tileSum[t] : 0;
    sh[t] = v;
    __syncthreads();
#pragma unroll
    for (int o = 1; o < 512; o <<= 1) {
        int a = (t >= o) ? sh[t - o] : 0;
        __syncthreads();
        sh[t] += a;
        __syncthreads();
    }
    if (t < NTILES) tileBase[t] = sh[t] - v;   // exclusive
}

__global__ void k_scan_within(const int* __restrict__ cnt,
                              const int* __restrict__ tileBase,
                              int* __restrict__ off, int* __restrict__ cursor) {
    __shared__ int sh[256];
    int t = threadIdx.x;
    int i = blockIdx.x * 256 + t;
    int v = (i < NN) ? cnt[i] : 0;
    sh[t] = v;
    __syncthreads();
#pragma unroll
    for (int o = 1; o < 256; o <<= 1) {
        int a = (t >= o) ? sh[t - o] : 0;
        __syncthreads();
        sh[t] += a;
        __syncthreads();
    }
    int incl = sh[t];
    if (i < NN) {
        int ex = tileBase[blockIdx.x] + incl - v;
        off[i] = ex;
        cursor[i] = ex;
        if (i == NN - 1) off[NN] = tileBase[blockIdx.x] + incl;
    }
}

__global__ void k_fill(const long long* __restrict__ ei,
                       const float* __restrict__ dinv,
                       int* __restrict__ cursor,
                       int2* __restrict__ csr) {
    int e = blockIdx.x * blockDim.x + threadIdx.x;
    if (e >= EE) return;
    int s, d;
    if (g_is64) {
        s = (int)ei[e];
        d = (int)ei[EE + e];
    } else {
        const int* ei32 = (const int*)ei;
        s = ei32[e];
        d = ei32[EE + e];
    }
    int pos = atomicAdd(&cursor[d], 1);
    csr[pos] = make_int2(s, __float_as_int(dinv[s] * dinv[d]));
}

// ---------------------------------------------------------------------------
// bf16 hi/lo splits
// ---------------------------------------------------------------------------
__device__ __forceinline__ void split2(float a, float b, uint32_t& h, uint32_t& l) {
    __nv_bfloat16 ha = __float2bfloat16(a);
    __nv_bfloat16 hb = __float2bfloat16(b);
    __nv_bfloat16 la = __float2bfloat16(a - __bfloat162float(ha));
    __nv_bfloat16 lb = __float2bfloat16(b - __bfloat162float(hb));
    __nv_bfloat162 hp = __halves2bfloat162(ha, hb);
    __nv_bfloat162 lp = __halves2bfloat162(la, lb);
    h = reinterpret_cast<uint32_t&>(hp);
    l = reinterpret_cast<uint32_t&>(lp);
}

__global__ void k_splitX(const float* __restrict__ x,
                         __nv_bfloat16* __restrict__ hi,
                         __nv_bfloat16* __restrict__ lo) {
    int idx = blockIdx.x * blockDim.x + threadIdx.x;   // per float4
    if (idx >= NN * FD / 4) return;
    float4 v = *(const float4*)(x + (size_t)idx * 4);
    uint2 hh, ll;
    split2(v.x, v.y, hh.x, ll.x);
    split2(v.z, v.w, hh.y, ll.y);
    *(uint2*)(hi + (size_t)idx * 4) = hh;
    *(uint2*)(lo + (size_t)idx * 4) = ll;
}

// Transposed weight split: out[n*128 + k] = split(W[k*Ncols + n])
__global__ void k_splitW(const float* __restrict__ W,
                         __nv_bfloat16* __restrict__ hi,
                         __nv_bfloat16* __restrict__ lo, int Ncols) {
    int idx = blockIdx.x * blockDim.x + threadIdx.x;
    if (idx >= Ncols * FD) return;
    int n = idx / FD, k = idx % FD;
    float v = W[(size_t)k * Ncols + n];
    __nv_bfloat16 h = __float2bfloat16(v);
    hi[idx] = h;
    lo[idx] = __float2bfloat16(v - __bfloat162float(h));
}

// ---------------------------------------------------------------------------
// Tensor-core GEMM (mma.sync bf16, 3-term split, fp32 accum, fp16 output)
// cp.async double-buffered K staging (2 x K=64 stages).
// ---------------------------------------------------------------------------
template <int BN>
__global__ void __launch_bounds__(256, 1)
k_mma(const __nv_bfloat16* __restrict__ Ahi, const __nv_bfloat16* __restrict__ Alo,
      const __nv_bfloat16* __restrict__ Bhi, const __nv_bfloat16* __restrict__ Blo,
      __half* __restrict__ H, int M) {
    constexpr int WM = (BN == 128) ? 4 : 8;        // warps along M
    constexpr int WN = 8 / WM;                     // warps along N
    constexpr int MA = 128 / (WM * 16);            // m16 atoms per warp
    constexpr int NA = (BN / WN) / 8;              // n8 atoms per warp

    extern __shared__ char smem[];
    const uint32_t sb  = smem_to_u32(smem);
    const uint32_t sAH = sb;
    const uint32_t sAL = sAH + 128 * KS * 2;
    const uint32_t sBH = sAL + 128 * KS * 2;
    const uint32_t sBL = sBH + BN * KS * 2;

    const int tid  = threadIdx.x;
    const int wid  = tid >> 5;
    const int lane = tid & 31;
    const int row0 = blockIdx.x * 128;
    const int wm   = wid % WM;
    const int wn   = wid / WM;
    const int rbase = wm * (128 / WM);             // warp row base in tile
    const int cbase = wn * (BN / WN);              // warp col base in tile

    int rows_valid = M - row0;
    if (rows_valid > 128) rows_valid = 128;
    const __nv_bfloat16* Ah = Ahi + (size_t)row0 * 128;
    const __nv_bfloat16* Al = Alo + (size_t)row0 * 128;

    // --- stage s covers K chunks [s*8, s*8+8) (chunk = 8 bf16 = 16 B) ---
    auto stage = [&](int s) {
        for (int idx = tid; idx < 128 * 8; idx += 256) {
            int row = idx >> 3;
            int c   = s * 8 + (idx & 7);
            uint32_t o = (uint32_t)(row * KS + c * 8) * 2;
            int sz = (row < rows_valid) ? 16 : 0;
            cp_async16(sAH + o, Ah + (size_t)row * 128 + c * 8, sz);
            cp_async16(sAL + o, Al + (size_t)row * 128 + c * 8, sz);
        }
        for (int idx = tid; idx < BN * 8; idx += 256) {
            int row = idx >> 3;
            int c   = s * 8 + (idx & 7);
            uint32_t o = (uint32_t)(row * KS + c * 8) * 2;
            cp_async16(sBH + o, Bhi + (size_t)row * 128 + c * 8, 16);
            cp_async16(sBL + o, Blo + (size_t)row * 128 + c * 8, 16);
        }
    };
    stage(0); CP_COMMIT();
    stage(1); CP_COMMIT();

    float acc[MA][NA][4];
#pragma unroll
    for (int i = 0; i < MA; i++)
#pragma unroll
        for (int j = 0; j < NA; j++)
#pragma unroll
            for (int q = 0; q < 4; q++) acc[i][j][q] = 0.0f;

    // ldmatrix per-lane address components
    const int aq   = lane >> 3;                    // 0..3 quadrant
    const int aw   = lane & 7;
    const int arow = (aq & 1) * 8 + aw;            // row within 16-row tile
    const int acol = (aq >> 1) * 8;                // k offset 0/8
    const int brow = (aq >> 1) * 8 + aw;           // n offset within atom-pair
    const int bcol = (aq & 1) * 8;                 // k offset 0/8

    auto compute = [&](int ko) {
        const int k0 = ko * 16;
        uint32_t ah[MA][4], al[MA][4];
#pragma unroll
        for (int ma = 0; ma < MA; ma++) {
            uint32_t off = (uint32_t)((rbase + ma * 16 + arow) * KS + k0 + acol) * 2;
            ldsm_x4(ah[ma][0], ah[ma][1], ah[ma][2], ah[ma][3], sAH + off);
            ldsm_x4(al[ma][0], al[ma][1], al[ma][2], al[ma][3], sAL + off);
        }
        uint32_t bh[NA][2], bl[NA][2];
#pragma unroll
        for (int nbp = 0; nbp < NA / 2; nbp++) {
            uint32_t off = (uint32_t)((cbase + nbp * 16 + brow) * KS + k0 + bcol) * 2;
            ldsm_x4(bh[nbp * 2][0], bh[nbp * 2][1],
                    bh[nbp * 2 + 1][0], bh[nbp * 2 + 1][1], sBH + off);
            ldsm_x4(bl[nbp * 2][0], bl[nbp * 2][1],
                    bl[nbp * 2 + 1][0], bl[nbp * 2 + 1][1], sBL + off);
        }
#pragma unroll
        for (int ma = 0; ma < MA; ma++)
#pragma unroll
            for (int na = 0; na < NA; na++) {
                mma16816(acc[ma][na], ah[ma], bh[na]);   // AhBh
                mma16816(acc[ma][na], ah[ma], bl[na]);   // AhBl
                mma16816(acc[ma][na], al[ma], bh[na]);   // AlBh
            }
    };

    CP_WAIT(1);            // stage 0 landed (stage 1 still in flight)
    __syncthreads();
#pragma unroll
    for (int ko = 0; ko < 4; ko++) compute(ko);

    CP_WAIT(0);            // stage 1 landed
    __syncthreads();
#pragma unroll
    for (int ko = 4; ko < 8; ko++) compute(ko);

    // --- store accumulators as fp16 ---
    const int crow = lane >> 2;                    // 0..7
    const int ccol = (lane & 3) * 2;
#pragma unroll
    for (int ma = 0; ma < MA; ma++) {
        int r0 = row0 + rbase + ma * 16 + crow;
        int r1 = r0 + 8;
        bool ok0 = r0 < M, ok1 = r1 < M;
#pragma unroll
        for (int na = 0; na < NA; na++) {
            int c = cbase + na * 8 + ccol;
            if (ok0) *(__half2*)&H[(size_t)r0 * BN + c] =
                         __floats2half2_rn(acc[ma][na][0], acc[ma][na][1]);
            if (ok1) *(__half2*)&H[(size_t)r1 * BN + c] =
                         __floats2half2_rn(acc[ma][na][2], acc[ma][na][3]);
        }
    }
}

// ---------------------------------------------------------------------------
// CSR aggregation, 128-dim: one warp per dst node, fp16 gather, fp32 accum.
// ---------------------------------------------------------------------------
__device__ __forceinline__ void acc_h4(float4& acc, float w, uint2 raw) {
    __half2 p0 = reinterpret_cast<__half2&>(raw.x);
    __half2 p1 = reinterpret_cast<__half2&>(raw.y);
    float2 f0 = __half22float2(p0);
    float2 f1 = __half22float2(p1);
    acc.x = fmaf(f0.x, w, acc.x);
    acc.y = fmaf(f0.y, w, acc.y);
    acc.z = fmaf(f1.x, w, acc.z);
    acc.w = fmaf(f1.y, w, acc.w);
}

__global__ void k_agg128(const __half* __restrict__ H,
                         __nv_bfloat16* __restrict__ Ghi,
                         __nv_bfloat16* __restrict__ Glo,
                         const int2* __restrict__ csr,
                         const int* __restrict__ off,
                         const float* __restrict__ dinv,
                         const float* __restrict__ bias) {
    int t = blockIdx.x * blockDim.x + threadIdx.x;
    int i = t >> 5;
    if (i >= NN) return;
    int lane = t & 31;

    float dv = dinv[i];
    float w0 = dv * dv;
    float4 acc = *(const float4*)&bias[lane * 4];
    acc_h4(acc, w0, *(const uint2*)(H + (size_t)i * 128 + lane * 4));

    int beg = off[i], end = off[i + 1];
    int j = beg;
    for (; j + 8 <= end; j += 8) {
        int2 e[8];
        uint2 r[8];
#pragma unroll
        for (int q = 0; q < 8; q++) e[q] = csr[j + q];
#pragma unroll
        for (int q = 0; q < 8; q++)
            r[q] = *(const uint2*)(H + (size_t)e[q].x * 128 + lane * 4);
#pragma unroll
        for (int q = 0; q < 8; q++)
            acc_h4(acc, __int_as_float(e[q].y), r[q]);
    }
    for (; j + 2 <= end; j += 2) {
        int2 e0 = csr[j], e1 = csr[j + 1];
        uint2 r0 = *(const uint2*)(H + (size_t)e0.x * 128 + lane * 4);
        uint2 r1 = *(const uint2*)(H + (size_t)e1.x * 128 + lane * 4);
        acc_h4(acc, __int_as_float(e0.y), r0);
        acc_h4(acc, __int_as_float(e1.y), r1);
    }
    if (j < end) {
        int2 e = csr[j];
        acc_h4(acc, __int_as_float(e.y),
               *(const uint2*)(H + (size_t)e.x * 128 + lane * 4));
    }

    // ReLU + hi/lo bf16 split (next layer's GEMM input)
    float vx = fmaxf(acc.x, 0.f), vy = fmaxf(acc.y, 0.f);
    float vz = fmaxf(acc.z, 0.f), vw = fmaxf(acc.w, 0.f);
    uint2 hh, ll;
    split2(vx, vy, hh.x, ll.x);
    split2(vz, vw, hh.y, ll.y);
    *(uint2*)(Ghi + (size_t)i * 128 + lane * 4) = hh;
    *(uint2*)(Glo + (size_t)i * 128 + lane * 4) = ll;
}

// ---------------------------------------------------------------------------
// CSR aggregation, 32-dim + fused log-softmax: 8 lanes per node, fp16 gather.
// ---------------------------------------------------------------------------
__global__ void k_agg32_lsm(const __half* __restrict__ H, float* __restrict__ out,
                            const int2* __restrict__ csr,
                            const int* __restrict__ off,
                            const float* __restrict__ dinv,
                            const float* __restrict__ bias) {
    int t = blockIdx.x * blockDim.x + threadIdx.x;
    int i = t >> 3;
    if (i >= NN) return;
    int sub = t & 7;

    float dv = dinv[i];
    float w0 = dv * dv;
    float4 acc = *(const float4*)&bias[sub * 4];
    acc_h4(acc, w0, *(const uint2*)(H + (size_t)i * 32 + sub * 4));

    int beg = off[i], end = off[i + 1];
    int j = beg;
    for (; j + 4 <= end; j += 4) {
        int2 e0 = csr[j],     e1 = csr[j + 1];
        int2 e2 = csr[j + 2], e3 = csr[j + 3];
        uint2 r0 = *(const uint2*)(H + (size_t)e0.x * 32 + sub * 4);
        uint2 r1 = *(const uint2*)(H + (size_t)e1.x * 32 + sub * 4);
        uint2 r2 = *(const uint2*)(H + (size_t)e2.x * 32 + sub * 4);
        uint2 r3 = *(const uint2*)(H + (size_t)e3.x * 32 + sub * 4);
        acc_h4(acc, __int_as_float(e0.y), r0);
        acc_h4(acc, __int_as_float(e1.y), r1);
        acc_h4(acc, __int_as_float(e2.y), r2);
        acc_h4(acc, __int_as_float(e3.y), r3);
    }
    for (; j < end; j++) {
        int2 e = csr[j];
        acc_h4(acc, __int_as_float(e.y),
               *(const uint2*)(H + (size_t)e.x * 32 + sub * 4));
    }

    unsigned m = __activemask();
    float mx = fmaxf(fmaxf(acc.x, acc.y), fmaxf(acc.z, acc.w));
#pragma unroll
    for (int o = 4; o > 0; o >>= 1)
        mx = fmaxf(mx, __shfl_xor_sync(m, mx, o));
    float ex = expf(acc.x - mx) + expf(acc.y - mx) +
               expf(acc.z - mx) + expf(acc.w - mx);
#pragma unroll
    for (int o = 4; o > 0; o >>= 1)
        ex += __shfl_xor_sync(m, ex, o);
    float ls = mx + logf(ex);

    float4 r;
    r.x = acc.x - ls; r.y = acc.y - ls; r.z = acc.z - ls; r.w = acc.w - ls;
    *(float4*)&out[(size_t)i * 32 + sub * 4] = r;
}

// ---------------------------------------------------------------------------
// Launch: CSR build forked onto a side stream, overlapped with splits + GEMM1.
// ---------------------------------------------------------------------------
extern "C" void kernel_launch(void* const* d_in, const int* in_sizes, int n_in,
                              void* d_out, int out_size) {
    const float*     x  = (const float*)d_in[0];
    const long long* ei = (const long long*)d_in[1];
    const float* W1 = (const float*)d_in[2];
    const float* b1 = (const float*)d_in[3];
    const float* W2 = (const float*)d_in[4];
    const float* b2 = (const float*)d_in[5];
    const float* W3 = (const float*)d_in[6];
    const float* b3 = (const float*)d_in[7];
    const float* W4 = (const float*)d_in[8];
    const float* b4 = (const float*)d_in[9];
    float* out = (float*)d_out;

    __half* H;
    float *dinv;
    __nv_bfloat16 *Ahi, *Alo, *Whi, *Wlo, *W4hi, *W4lo;
    int *cnt, *off, *cursor, *tileSum, *tileBase;
    int2* csr;
    cudaGetSymbolAddress((void**)&H,        g_H);
    cudaGetSymbolAddress((void**)&Ahi,      g_Ahi);
    cudaGetSymbolAddress((void**)&Alo,      g_Alo);
    cudaGetSymbolAddress((void**)&dinv,     g_dinv);
    cudaGetSymbolAddress((void**)&cnt,      g_cnt);
    cudaGetSymbolAddress((void**)&off,      g_off);
    cudaGetSymbolAddress((void**)&cursor,   g_cursor);
    cudaGetSymbolAddress((void**)&tileSum,  g_tileSum);
    cudaGetSymbolAddress((void**)&tileBase, g_tileBase);
    cudaGetSymbolAddress((void**)&csr,      g_csr);
    cudaGetSymbolAddress((void**)&Whi,      g_Whi);
    cudaGetSymbolAddress((void**)&Wlo,      g_Wlo);
    cudaGetSymbolAddress((void**)&W4hi,     g_W4hi);
    cudaGetSymbolAddress((void**)&W4lo,     g_W4lo);

    const int TB = 256;
    const int nblk = NTILES;
    const int eblk = (EE + TB - 1) / TB;

    // dynamic smem: (128 + 128 + BN + BN) rows * KS bf16
    const int SMEM128 = (128 + 128 + 128 + 128) * KS * 2;   // 139264
    const int SMEM32  = (128 + 128 + 32 + 32) * KS * 2;     // 87040
    cudaFuncSetAttribute((const void*)k_mma<128>,
                         cudaFuncAttributeMaxDynamicSharedMemorySize, SMEM128);
    cudaFuncSetAttribute((const void*)k_mma<32>,
                         cudaFuncAttributeMaxDynamicSharedMemorySize, SMEM32);

    // Side stream + fork/join events (created per call; few calls total, and
    // they must outlive graph capture, so they are intentionally not destroyed).
    cudaStream_t s2;
    cudaStreamCreateWithFlags(&s2, cudaStreamNonBlocking);
    cudaEvent_t evFork, evJoin;
    cudaEventCreateWithFlags(&evFork, cudaEventDisableTiming);
    cudaEventCreateWithFlags(&evJoin, cudaEventDisableTiming);

    // --- fork: CSR build on s2 ---
    cudaEventRecord(evFork, 0);
    cudaStreamWaitEvent(s2, evFork, 0);
    k_detect_dtype<<<1, 32, 0, s2>>>(ei);
    k_zero_cnt<<<nblk, TB, 0, s2>>>(cnt);
    k_hist<<<eblk, TB, 0, s2>>>(ei, cnt);
    k_dinv<<<nblk, TB, 0, s2>>>(cnt, dinv);
    k_tile_sums<<<nblk, TB, 0, s2>>>(cnt, tileSum);
    k_scan_tilesums<<<1, 512, 0, s2>>>(tileSum, tileBase);
    k_scan_within<<<nblk, TB, 0, s2>>>(cnt, tileBase, off, cursor);
    k_fill<<<eblk, TB, 0, s2>>>(ei, dinv, cursor, csr);
    cudaEventRecord(evJoin, s2);

    // --- main stream: splits + layer-1 GEMM (independent of CSR) ---
    k_splitX<<<(NN * FD / 4 + TB - 1) / TB, TB>>>(x, Ahi, Alo);
    k_splitW<<<(FD * FD + TB - 1) / TB, TB>>>(W1, Whi + 0 * FD * FD, Wlo + 0 * FD * FD, FD);
    k_splitW<<<(FD * FD + TB - 1) / TB, TB>>>(W2, Whi + 1 * FD * FD, Wlo + 1 * FD * FD, FD);
    k_splitW<<<(FD * FD + TB - 1) / TB, TB>>>(W3, Whi + 2 * FD * FD, Wlo + 2 * FD * FD, FD);
    k_splitW<<<(CD * FD + TB - 1) / TB, TB>>>(W4, W4hi, W4lo, CD);

    const int mma_grid = (NN + 127) / 128;   // 782
    const int agg128_blocks = (NN * 32 + TB - 1) / TB;
    const int agg32_blocks  = (NN * 8 + TB - 1) / TB;

    // --- layer 1 ---
    k_mma<128><<<mma_grid, 256, SMEM128>>>(Ahi, Alo, Whi + 0 * FD * FD, Wlo + 0 * FD * FD, H, NN);
    cudaStreamWaitEvent(0, evJoin, 0);       // join: agg needs csr/off/dinv
    k_agg128<<<agg128_blocks, TB>>>(H, Ahi, Alo, csr, off, dinv, b1);

    // --- layer 2 ---
    k_mma<128><<<mma_grid, 256, SMEM128>>>(Ahi, Alo, Whi + 1 * FD * FD, Wlo + 1 * FD * FD, H, NN);
    k_agg128<<<agg128_blocks, TB>>>(H, Ahi, Alo, csr, off, dinv, b2);

    // --- layer 3 ---
    k_mma<128><<<mma_grid, 256, SMEM128>>>(Ahi, Alo, Whi + 2 * FD * FD, Wlo + 2 * FD * FD, H, NN);
    k_agg128<<<agg128_blocks, TB>>>(H, Ahi, Alo, csr, off, dinv, b3);

    // --- layer 4 (32 classes) + fused log-softmax ---
    k_mma<32><<<mma_grid, 256, SMEM32>>>(Ahi, Alo, W4hi, W4lo, H, NN);
    k_agg32_lsm<<<agg32_blocks, TB>>>(H, out, csr, off, dinv, b4);
}